// round 12
// baseline (speedup 1.0000x reference)
#include <cuda_runtime.h>
#include <cuda_fp16.h>
#include <math.h>
#include <cstdint>

// Problem constants
#define B 4
#define C 64
#define NA 25
#define H 64
#define W 64
#define S 320        // H*U
#define NCHUNK 320   // chunks of 64 floats along w
#define D_TOT 20480  // feature dim
#define BSTRIDE 6553600
#define CSTRIDE 102400
#define NSTRIDE 4096
#define SK 16                       // split-K for scores
#define KSTEPS (D_TOT / SK / 64)    // 20 K-blocks of 64 per split

typedef unsigned long long u64;

// ---- scratch (device globals; no allocations allowed) ----
__device__ float g_rq[B * S];
__device__ float g_rk[B * S];
__device__ float g_attp[(size_t)SK * B * S * S];   // split-K partial scores (f32)
__device__ __half g_attb[(size_t)B * S * S];       // softmax probs (f16)
__device__ __half g_qb[(size_t)B * S * D_TOT];
__device__ __half g_kb[(size_t)B * S * D_TOT];
__device__ __half g_vb[(size_t)B * S * D_TOT];

// original-layout address of (b, s, chunk ck, w=0)
__device__ __forceinline__ size_t elem_base(int b, int s, int ck) {
    int h = s / 5, uu = s - h * 5;
    int c = ck / 5, vv = ck - c * 5;
    return (size_t)b * BSTRIDE + (size_t)c * CSTRIDE + (size_t)(uu * 5 + vv) * NSTRIDE + (size_t)h * W;
}

// ---- PTX helpers (sm_80-level: valid at virtual target sm_103) ----
__device__ __forceinline__ uint32_t smem_u32(const void* p) {
    uint32_t a;
    asm("{ .reg .u64 t; cvta.to.shared.u64 t, %1; cvt.u32.u64 %0, t; }" : "=r"(a) : "l"(p));
    return a;
}
__device__ __forceinline__ void cpa16(uint32_t dst, const void* src) {
    asm volatile("{ .reg .u64 g; cvta.to.global.u64 g, %1; cp.async.cg.shared.global [%0], [g], 16; }"
                 :: "r"(dst), "l"(src) : "memory");
}
#define CP_COMMIT() asm volatile("cp.async.commit_group;" ::: "memory")
#define CP_WAIT0()  asm volatile("cp.async.wait_group 0;" ::: "memory")
#define CP_WAIT1()  asm volatile("cp.async.wait_group 1;" ::: "memory")

__device__ __forceinline__ void ldm4(uint32_t* r, uint32_t addr) {
    asm volatile("ldmatrix.sync.aligned.m8n8.x4.shared.b16 {%0,%1,%2,%3}, [%4];"
                 : "=r"(r[0]), "=r"(r[1]), "=r"(r[2]), "=r"(r[3]) : "r"(addr));
}
__device__ __forceinline__ void ldm4t(uint32_t* r, uint32_t addr) {
    asm volatile("ldmatrix.sync.aligned.m8n8.x4.trans.shared.b16 {%0,%1,%2,%3}, [%4];"
                 : "=r"(r[0]), "=r"(r[1]), "=r"(r[2]), "=r"(r[3]) : "r"(addr));
}
__device__ __forceinline__ void mma_f16(float* d, const uint32_t* a, const uint32_t* b) {
    asm volatile("mma.sync.aligned.m16n8k16.row.col.f32.f16.f16.f32 "
                 "{%0,%1,%2,%3}, {%4,%5,%6,%7}, {%8,%9}, {%0,%1,%2,%3};"
                 : "+f"(d[0]), "+f"(d[1]), "+f"(d[2]), "+f"(d[3])
                 : "r"(a[0]), "r"(a[1]), "r"(a[2]), "r"(a[3]), "r"(b[0]), "r"(b[1]));
}

// pack 8 f32 -> 8 f16 in a uint4
__device__ __forceinline__ uint4 pack8(float4 x0, float4 x1) {
    uint4 wv;
    __half2 p0 = __floats2half2_rn(x0.x, x0.y);
    __half2 p1 = __floats2half2_rn(x0.z, x0.w);
    __half2 p2 = __floats2half2_rn(x1.x, x1.y);
    __half2 p3 = __floats2half2_rn(x1.z, x1.w);
    *reinterpret_cast<__half2*>(&wv.x) = p0;
    *reinterpret_cast<__half2*>(&wv.y) = p1;
    *reinterpret_cast<__half2*>(&wv.z) = p2;
    *reinterpret_cast<__half2*>(&wv.w) = p3;
    return wv;
}

// ---------------------------------------------------------------------------
// K1a: gather + f16 convert (Q, K) + row inverse-norms.  8 floats/thread/iter.
// grid (B*S, 2), 256 threads.
// ---------------------------------------------------------------------------
__global__ __launch_bounds__(256) void conv_qk_kernel(const float* __restrict__ q,
                                                      const float* __restrict__ k) {
    int row = blockIdx.x;
    int which = blockIdx.y;
    const float* src = which ? k : q;
    __half* dstb = which ? g_kb : g_qb;
    int b = row / S, s = row - b * S;

    uint4* drow = (uint4*)(dstb + (size_t)row * D_TOT);
    float acc = 0.f;
    #pragma unroll 2
    for (int i = threadIdx.x; i < NCHUNK * 8; i += 256) {
        int ck = i >> 3, f8 = i & 7;
        const float* base = src + elem_base(b, s, ck) + f8 * 8;
        float4 x0 = *(const float4*)base;
        float4 x1 = *(const float4*)(base + 4);
        acc += x0.x * x0.x + x0.y * x0.y + x0.z * x0.z + x0.w * x0.w
             + x1.x * x1.x + x1.y * x1.y + x1.z * x1.z + x1.w * x1.w;
        drow[i] = pack8(x0, x1);
    }
    __shared__ float red[256];
    red[threadIdx.x] = acc;
    __syncthreads();
    for (int off = 128; off; off >>= 1) {
        if (threadIdx.x < off) red[threadIdx.x] += red[threadIdx.x + off];
        __syncthreads();
    }
    if (threadIdx.x == 0)
        (which ? g_rk : g_rq)[row] = 1.f / fmaxf(sqrtf(red[0]), 1e-12f);
}

// ---------------------------------------------------------------------------
// K1b: gather + f16 convert of V only.  grid B*S, 256 threads.
// Launched on s2 AFTER conv_qk: overlaps the tensor-bound scores+softmax.
// ---------------------------------------------------------------------------
__global__ __launch_bounds__(256) void conv_v_kernel(const float* __restrict__ v) {
    int row = blockIdx.x;
    int b = row / S, s = row - b * S;
    uint4* drow = (uint4*)(g_vb + (size_t)row * D_TOT);
    #pragma unroll 2
    for (int i = threadIdx.x; i < NCHUNK * 8; i += 256) {
        int ck = i >> 3, f8 = i & 7;
        const float* base = v + elem_base(b, s, ck) + f8 * 8;
        float4 x0 = *(const float4*)base;
        float4 x1 = *(const float4*)(base + 4);
        drow[i] = pack8(x0, x1);
    }
}

// ---------------------------------------------------------------------------
// K2: scores = Q K^T via mma.sync f16.  Tile 128x128, K-blocks of 64,
// split-K=16.  cp.async double buffer, XOR-swizzled smem, causal tile list.
// grid (6 pairs, 16 splits, B), 256 threads, 64KB dynamic smem.
// ---------------------------------------------------------------------------
#define SC_A0 0
#define SC_A1 16384
#define SC_B0 32768
#define SC_B1 49152
#define SC_SMEM 65536

__global__ __launch_bounds__(256) void scores_mma() {
    extern __shared__ char sm[];
    uint32_t sb = smem_u32(sm);
    const int MI[6] = {0, 1, 1, 2, 2, 2};
    const int NJ[6] = {0, 0, 1, 0, 1, 2};
    int pair = blockIdx.x, split = blockIdx.y, b = blockIdx.z;
    int s0 = MI[pair] * 128, t0 = NJ[pair] * 128;
    int tid = threadIdx.x, l = tid & 31, wid = tid >> 5;
    int wm = wid >> 2, wn = wid & 3;    // warp grid 2 (M) x 4 (N)
    int d_base = split * (D_TOT / SK);

    const __half* qrow = g_qb + (size_t)b * S * D_TOT;
    const __half* krow = g_kb + (size_t)b * S * D_TOT;

    float acc[4][4][4];
    #pragma unroll
    for (int f = 0; f < 4; f++)
        #pragma unroll
        for (int nf = 0; nf < 4; nf++)
            #pragma unroll
            for (int e = 0; e < 4; e++) acc[f][nf][e] = 0.f;

    const uint32_t AOF[2] = {SC_A0, SC_A1}, BOF[2] = {SC_B0, SC_B1};

    // fill step 0
    {
        int d0 = d_base;
        #pragma unroll
        for (int j = 0; j < 4; j++) {
            int idx = tid + 256 * j, r = idx >> 3, g = idx & 7;
            int s = s0 + r; if (s >= S) s = S - 1;
            cpa16(sb + SC_A0 + r * 128 + ((g ^ (r & 7)) << 4), qrow + (size_t)s * D_TOT + d0 + g * 8);
        }
        #pragma unroll
        for (int j = 0; j < 4; j++) {
            int idx = tid + 256 * j, r = idx >> 3, g = idx & 7;
            int t = t0 + r; if (t >= S) t = S - 1;
            cpa16(sb + SC_B0 + r * 128 + ((g ^ (r & 7)) << 4), krow + (size_t)t * D_TOT + d0 + g * 8);
        }
        CP_COMMIT();
    }

    for (int step = 0; step < KSTEPS; step++) {
        int buf = step & 1;
        if (step + 1 < KSTEPS) {
            int d0 = d_base + (step + 1) * 64;
            uint32_t a_of = AOF[buf ^ 1], b_of = BOF[buf ^ 1];
            #pragma unroll
            for (int j = 0; j < 4; j++) {
                int idx = tid + 256 * j, r = idx >> 3, g = idx & 7;
                int s = s0 + r; if (s >= S) s = S - 1;
                cpa16(sb + a_of + r * 128 + ((g ^ (r & 7)) << 4), qrow + (size_t)s * D_TOT + d0 + g * 8);
            }
            #pragma unroll
            for (int j = 0; j < 4; j++) {
                int idx = tid + 256 * j, r = idx >> 3, g = idx & 7;
                int t = t0 + r; if (t >= S) t = S - 1;
                cpa16(sb + b_of + r * 128 + ((g ^ (r & 7)) << 4), krow + (size_t)t * D_TOT + d0 + g * 8);
            }
            CP_COMMIT();
            CP_WAIT1();
        } else {
            CP_WAIT0();
        }
        __syncthreads();
        uint32_t Ab = sb + AOF[buf], Bb = sb + BOF[buf];
        #pragma unroll
        for (int kk = 0; kk < 4; kk++) {
            uint32_t af[4][4], bfr[2][4];
            #pragma unroll
            for (int f = 0; f < 4; f++) {
                int rowA = wm * 64 + f * 16 + (l & 15);
                int g = 2 * kk + (l >> 4);
                ldm4(af[f], Ab + rowA * 128 + ((g ^ (l & 7)) << 4));
            }
            #pragma unroll
            for (int h = 0; h < 2; h++) {
                int rowB = wn * 32 + h * 16 + (l & 7) + ((l >> 4) << 3);
                int g = 2 * kk + ((l >> 3) & 1);
                ldm4(bfr[h], Bb + rowB * 128 + ((g ^ (rowB & 7)) << 4));
            }
            #pragma unroll
            for (int f = 0; f < 4; f++)
                #pragma unroll
                for (int nf = 0; nf < 4; nf++)
                    mma_f16(acc[f][nf], af[f], &bfr[nf >> 1][(nf & 1) * 2]);
        }
        __syncthreads();
    }

    // epilogue: apply rq*rk, store split partials
    float* outp = g_attp + (size_t)split * (B * S * S) + (size_t)b * S * S;
    #pragma unroll
    for (int f = 0; f < 4; f++) {
        int r0 = s0 + wm * 64 + f * 16 + (l >> 2);
        #pragma unroll
        for (int half = 0; half < 2; half++) {
            int s = r0 + half * 8;
            if (s < S) {
                float rq = __ldg(&g_rq[b * S + s]);
                #pragma unroll
                for (int nf = 0; nf < 4; nf++) {
                    int t = t0 + wn * 32 + nf * 8 + (l & 3) * 2;
                    if (t < S) {
                        float2 o;
                        o.x = acc[f][nf][half * 2 + 0] * rq * __ldg(&g_rk[b * S + t]);
                        o.y = acc[f][nf][half * 2 + 1] * rq * __ldg(&g_rk[b * S + t + 1]);
                        *(float2*)(outp + (size_t)s * S + t) = o;
                    }
                }
            }
        }
    }
}

// ---------------------------------------------------------------------------
// K3: split-K reduce + causal softmax -> f16 probabilities.
// grid B*S, 320 threads.
// ---------------------------------------------------------------------------
__global__ __launch_bounds__(S) void softmax_kernel() {
    int row = blockIdx.x;
    int s = row % S;
    int tid = threadIdx.x;
    __shared__ float red[10];

    float x;
    if (tid <= s) {
        x = 0.f;
        #pragma unroll
        for (int sp = 0; sp < SK; sp++)
            x += g_attp[(size_t)sp * (B * S * S) + (size_t)row * S + tid];
    } else {
        x = -1e30f;
    }
    float m = x;
    #pragma unroll
    for (int o = 16; o; o >>= 1) m = fmaxf(m, __shfl_xor_sync(0xffffffffu, m, o));
    if ((tid & 31) == 0) red[tid >> 5] = m;
    __syncthreads();
    float mall = red[0];
    #pragma unroll
    for (int i = 1; i < 10; i++) mall = fmaxf(mall, red[i]);

    float e = (tid <= s) ? expf(x - mall) : 0.f;
    float ssum = e;
    #pragma unroll
    for (int o = 16; o; o >>= 1) ssum += __shfl_xor_sync(0xffffffffu, ssum, o);
    __syncthreads();
    if ((tid & 31) == 0) red[tid >> 5] = ssum;
    __syncthreads();
    float tot = 0.f;
    #pragma unroll
    for (int i = 0; i < 10; i++) tot += red[i];

    g_attb[(size_t)row * S + tid] = __float2half(e / tot);
}

// ---------------------------------------------------------------------------
// K4: out = att @ V + residual via mma.sync f16.  Tile M=64(s) x N=128(d),
// K = t-blocks of 64 (causal: stile+1 blocks).  2-stage, 48KB smem -> 4 CTAs/SM.
// grid (160, 5, B), 256 threads.
// ---------------------------------------------------------------------------
#define OU_A0 0
#define OU_A1 8192
#define OU_B0 16384
#define OU_B1 32768
#define OU_SMEM 49152

__global__ __launch_bounds__(256) void out_mma(const float* __restrict__ v,
                                               float* __restrict__ out) {
    extern __shared__ char sm[];
    uint32_t sb = smem_u32(sm);
    int ckp = blockIdx.x, stile = blockIdx.y, b = blockIdx.z;
    int s0 = stile * 64, n0 = ckp * 128;
    int tid = threadIdx.x, l = tid & 31, wid = tid >> 5;
    int wm = wid >> 2, wn = wid & 3;    // warp grid 2 (M: 32 rows) x 4 (N: 32 cols)
    int nblocks = stile + 1;

    const __half* pb = g_attb + (size_t)b * S * S;
    const __half* vb = g_vb + (size_t)b * S * D_TOT;

    float acc[2][4][4];
    #pragma unroll
    for (int f = 0; f < 2; f++)
        #pragma unroll
        for (int nf = 0; nf < 4; nf++)
            #pragma unroll
            for (int e = 0; e < 4; e++) acc[f][nf][e] = 0.f;

    const uint32_t AOF[2] = {OU_A0, OU_A1}, BOF[2] = {OU_B0, OU_B1};

    // fill block 0: A = att tile 64x64 (128B rows), B = V tile 64x128 (256B rows)
    {
        #pragma unroll
        for (int j = 0; j < 2; j++) {
            int idx = tid + 256 * j, r = idx >> 3, g = idx & 7;
            cpa16(sb + OU_A0 + r * 128 + ((g ^ (r & 7)) << 4), pb + (size_t)(s0 + r) * S + g * 8);
        }
        #pragma unroll
        for (int j = 0; j < 4; j++) {
            int idx = tid + 256 * j, r = idx >> 4, g = idx & 15;
            cpa16(sb + OU_B0 + r * 256 + ((g ^ (r & 7)) << 4), vb + (size_t)r * D_TOT + n0 + g * 8);
        }
        CP_COMMIT();
    }

    for (int tt = 0; tt < nblocks; tt++) {
        int buf = tt & 1;
        if (tt + 1 < nblocks) {
            int t1 = (tt + 1) * 64;
            uint32_t a_of = AOF[buf ^ 1], b_of = BOF[buf ^ 1];
            #pragma unroll
            for (int j = 0; j < 2; j++) {
                int idx = tid + 256 * j, r = idx >> 3, g = idx & 7;
                cpa16(sb + a_of + r * 128 + ((g ^ (r & 7)) << 4), pb + (size_t)(s0 + r) * S + t1 + g * 8);
            }
            #pragma unroll
            for (int j = 0; j < 4; j++) {
                int idx = tid + 256 * j, r = idx >> 4, g = idx & 15;
                cpa16(sb + b_of + r * 256 + ((g ^ (r & 7)) << 4), vb + (size_t)(t1 + r) * D_TOT + n0 + g * 8);
            }
            CP_COMMIT();
            CP_WAIT1();
        } else {
            CP_WAIT0();
        }
        __syncthreads();
        uint32_t Ab = sb + AOF[buf], Bb = sb + BOF[buf];
        #pragma unroll
        for (int kk = 0; kk < 4; kk++) {
            uint32_t af[2][4], bfr[2][4];
            #pragma unroll
            for (int f = 0; f < 2; f++) {
                int rowA = wm * 32 + f * 16 + (l & 15);
                int g = 2 * kk + (l >> 4);
                ldm4(af[f], Ab + rowA * 128 + ((g ^ (l & 7)) << 4));
            }
            #pragma unroll
            for (int h = 0; h < 2; h++) {
                int rowB = kk * 16 + (l & 15);
                int g = wn * 4 + h * 2 + (l >> 4);
                ldm4t(bfr[h], Bb + rowB * 256 + ((g ^ (rowB & 7)) << 4));
            }
            #pragma unroll
            for (int f = 0; f < 2; f++)
                #pragma unroll
                for (int nf = 0; nf < 4; nf++)
                    mma_f16(acc[f][nf], af[f], &bfr[nf >> 1][(nf & 1) * 2]);
        }
        __syncthreads();
    }

    // epilogue: residual add (fp32 token_v) + store to original layout
    #pragma unroll
    for (int f = 0; f < 2; f++) {
        #pragma unroll
        for (int half = 0; half < 2; half++) {
            int s = s0 + wm * 32 + f * 16 + (l >> 2) + half * 8;
            #pragma unroll
            for (int nf = 0; nf < 4; nf++) {
                int d = n0 + wn * 32 + nf * 8 + (l & 3) * 2;
                int ck = d >> 6, w = d & 63;
                size_t g = elem_base(b, s, ck) + w;
                float2 vv = *(const float2*)(v + g);
                float2 o;
                o.x = acc[f][nf][half * 2 + 0] + vv.x;
                o.y = acc[f][nf][half * 2 + 1] + vv.y;
                *(float2*)(out + g) = o;
            }
        }
    }
}

// ---------------------------------------------------------------------------
extern "C" void kernel_launch(void* const* d_in, const int* in_sizes, int n_in,
                              void* d_out, int out_size) {
    const float* q = (const float*)d_in[0];
    const float* k = (const float*)d_in[1];
    const float* v = (const float*)d_in[2];
    float* out = (float*)d_out;

    static bool init_done = false;
    static cudaStream_t s2;
    static cudaEvent_t ev_qk, ev_vdone;
    if (!init_done) {
        cudaFuncSetAttribute(scores_mma, cudaFuncAttributeMaxDynamicSharedMemorySize, SC_SMEM);
        cudaFuncSetAttribute(out_mma, cudaFuncAttributeMaxDynamicSharedMemorySize, OU_SMEM);
        cudaStreamCreateWithFlags(&s2, cudaStreamNonBlocking);
        cudaEventCreateWithFlags(&ev_qk, cudaEventDisableTiming);
        cudaEventCreateWithFlags(&ev_vdone, cudaEventDisableTiming);
        init_done = true;
    }

    // main: conv_qk (DRAM-bound, runs alone at full BW)
    conv_qk_kernel<<<dim3(B * S, 2), 256>>>(q, k);

    // fork: conv_v (DRAM-bound) overlaps scores+softmax (tensor/L2-bound)
    cudaEventRecord(ev_qk, 0);
    cudaStreamWaitEvent(s2, ev_qk, 0);
    conv_v_kernel<<<B * S, 256, 0, s2>>>(v);

    scores_mma<<<dim3(6, SK, B), 256, SC_SMEM>>>();
    softmax_kernel<<<B * S, S>>>();

    // join conv_v -> out_mma
    cudaEventRecord(ev_vdone, s2);
    cudaStreamWaitEvent(0, ev_vdone, 0);
    out_mma<<<dim3(160, 5, B), 256, OU_SMEM>>>(v, out);
}

// round 13
// speedup vs baseline: 1.3229x; 1.3229x over previous
#include <cuda_runtime.h>
#include <cuda_fp16.h>
#include <math.h>
#include <cstdint>

// Problem constants
#define B 4
#define C 64
#define NA 25
#define H 64
#define W 64
#define S 320        // H*U
#define NCHUNK 320   // chunks of 64 floats along w
#define D_TOT 20480  // feature dim
#define BSTRIDE 6553600
#define CSTRIDE 102400
#define NSTRIDE 4096
#define SK 16                       // split-K for scores
#define KSTEPS (D_TOT / SK / 64)    // 20 K-blocks of 64 per split

typedef unsigned long long u64;

// ---- scratch (device globals; no allocations allowed) ----
__device__ float g_rq[B * S];
__device__ float g_rk[B * S];
__device__ float g_attp[(size_t)SK * B * S * S];   // split-K partial scores (f32)
__device__ __half g_attb[(size_t)B * S * S];       // softmax probs (f16)
__device__ __half g_qb[(size_t)B * S * D_TOT];
__device__ __half g_kb[(size_t)B * S * D_TOT];
__device__ __half g_vb[(size_t)B * S * D_TOT];

// original-layout address of (b, s, chunk ck, w=0)
__device__ __forceinline__ size_t elem_base(int b, int s, int ck) {
    int h = s / 5, uu = s - h * 5;
    int c = ck / 5, vv = ck - c * 5;
    return (size_t)b * BSTRIDE + (size_t)c * CSTRIDE + (size_t)(uu * 5 + vv) * NSTRIDE + (size_t)h * W;
}

// ---- PTX helpers (sm_80-level: valid at virtual target sm_103) ----
__device__ __forceinline__ uint32_t smem_u32(const void* p) {
    uint32_t a;
    asm("{ .reg .u64 t; cvta.to.shared.u64 t, %1; cvt.u32.u64 %0, t; }" : "=r"(a) : "l"(p));
    return a;
}
__device__ __forceinline__ void cpa16(uint32_t dst, const void* src) {
    asm volatile("{ .reg .u64 g; cvta.to.global.u64 g, %1; cp.async.cg.shared.global [%0], [g], 16; }"
                 :: "r"(dst), "l"(src) : "memory");
}
#define CP_COMMIT() asm volatile("cp.async.commit_group;" ::: "memory")
#define CP_WAIT0()  asm volatile("cp.async.wait_group 0;" ::: "memory")
#define CP_WAIT1()  asm volatile("cp.async.wait_group 1;" ::: "memory")

__device__ __forceinline__ void ldm4(uint32_t* r, uint32_t addr) {
    asm volatile("ldmatrix.sync.aligned.m8n8.x4.shared.b16 {%0,%1,%2,%3}, [%4];"
                 : "=r"(r[0]), "=r"(r[1]), "=r"(r[2]), "=r"(r[3]) : "r"(addr));
}
__device__ __forceinline__ void ldm4t(uint32_t* r, uint32_t addr) {
    asm volatile("ldmatrix.sync.aligned.m8n8.x4.trans.shared.b16 {%0,%1,%2,%3}, [%4];"
                 : "=r"(r[0]), "=r"(r[1]), "=r"(r[2]), "=r"(r[3]) : "r"(addr));
}
__device__ __forceinline__ void mma_f16(float* d, const uint32_t* a, const uint32_t* b) {
    asm volatile("mma.sync.aligned.m16n8k16.row.col.f32.f16.f16.f32 "
                 "{%0,%1,%2,%3}, {%4,%5,%6,%7}, {%8,%9}, {%0,%1,%2,%3};"
                 : "+f"(d[0]), "+f"(d[1]), "+f"(d[2]), "+f"(d[3])
                 : "r"(a[0]), "r"(a[1]), "r"(a[2]), "r"(a[3]), "r"(b[0]), "r"(b[1]));
}

// pack 8 f32 -> 8 f16 in a uint4
__device__ __forceinline__ uint4 pack8(float4 x0, float4 x1) {
    uint4 wv;
    __half2 p0 = __floats2half2_rn(x0.x, x0.y);
    __half2 p1 = __floats2half2_rn(x0.z, x0.w);
    __half2 p2 = __floats2half2_rn(x1.x, x1.y);
    __half2 p3 = __floats2half2_rn(x1.z, x1.w);
    *reinterpret_cast<__half2*>(&wv.x) = p0;
    *reinterpret_cast<__half2*>(&wv.y) = p1;
    *reinterpret_cast<__half2*>(&wv.z) = p2;
    *reinterpret_cast<__half2*>(&wv.w) = p3;
    return wv;
}

// ---------------------------------------------------------------------------
// K1: fused gather + f16 convert (Q, K, V) + row inverse-norms (Q, K).
// grid (B*S, 3), 256 threads.  8 floats/thread/iter (2 independent LDG.128).
// ---------------------------------------------------------------------------
__global__ __launch_bounds__(256) void convnorm_kernel(const float* __restrict__ q,
                                                       const float* __restrict__ k,
                                                       const float* __restrict__ v) {
    int row = blockIdx.x;
    int which = blockIdx.y;
    const float* src = (which == 0) ? q : (which == 1) ? k : v;
    __half* dstb = (which == 0) ? g_qb : (which == 1) ? g_kb : g_vb;
    int b = row / S, s = row - b * S;

    uint4* drow = (uint4*)(dstb + (size_t)row * D_TOT);
    float acc = 0.f;
    #pragma unroll 2
    for (int i = threadIdx.x; i < NCHUNK * 8; i += 256) {
        int ck = i >> 3, f8 = i & 7;
        const float* base = src + elem_base(b, s, ck) + f8 * 8;
        float4 x0 = *(const float4*)base;
        float4 x1 = *(const float4*)(base + 4);
        acc += x0.x * x0.x + x0.y * x0.y + x0.z * x0.z + x0.w * x0.w
             + x1.x * x1.x + x1.y * x1.y + x1.z * x1.z + x1.w * x1.w;
        drow[i] = pack8(x0, x1);
    }
    if (which < 2) {
        __shared__ float red[256];
        red[threadIdx.x] = acc;
        __syncthreads();
        for (int off = 128; off; off >>= 1) {
            if (threadIdx.x < off) red[threadIdx.x] += red[threadIdx.x + off];
            __syncthreads();
        }
        if (threadIdx.x == 0)
            (which ? g_rk : g_rq)[row] = 1.f / fmaxf(sqrtf(red[0]), 1e-12f);
    }
}

// ---------------------------------------------------------------------------
// K2: scores = Q K^T via mma.sync f16.  Tile 128x128, K-blocks of 64,
// split-K=16.  cp.async double buffer, XOR-swizzled smem, causal tile list.
// grid (6 pairs, 16 splits, B), 256 threads, 64KB dynamic smem.
// ---------------------------------------------------------------------------
#define SC_A0 0
#define SC_A1 16384
#define SC_B0 32768
#define SC_B1 49152
#define SC_SMEM 65536

__global__ __launch_bounds__(256) void scores_mma() {
    extern __shared__ char sm[];
    uint32_t sb = smem_u32(sm);
    const int MI[6] = {0, 1, 1, 2, 2, 2};
    const int NJ[6] = {0, 0, 1, 0, 1, 2};
    int pair = blockIdx.x, split = blockIdx.y, b = blockIdx.z;
    int s0 = MI[pair] * 128, t0 = NJ[pair] * 128;
    int tid = threadIdx.x, l = tid & 31, wid = tid >> 5;
    int wm = wid >> 2, wn = wid & 3;    // warp grid 2 (M) x 4 (N)
    int d_base = split * (D_TOT / SK);

    const __half* qrow = g_qb + (size_t)b * S * D_TOT;
    const __half* krow = g_kb + (size_t)b * S * D_TOT;

    float acc[4][4][4];
    #pragma unroll
    for (int f = 0; f < 4; f++)
        #pragma unroll
        for (int nf = 0; nf < 4; nf++)
            #pragma unroll
            for (int e = 0; e < 4; e++) acc[f][nf][e] = 0.f;

    const uint32_t AOF[2] = {SC_A0, SC_A1}, BOF[2] = {SC_B0, SC_B1};

    // fill step 0
    {
        int d0 = d_base;
        #pragma unroll
        for (int j = 0; j < 4; j++) {
            int idx = tid + 256 * j, r = idx >> 3, g = idx & 7;
            int s = s0 + r; if (s >= S) s = S - 1;
            cpa16(sb + SC_A0 + r * 128 + ((g ^ (r & 7)) << 4), qrow + (size_t)s * D_TOT + d0 + g * 8);
        }
        #pragma unroll
        for (int j = 0; j < 4; j++) {
            int idx = tid + 256 * j, r = idx >> 3, g = idx & 7;
            int t = t0 + r; if (t >= S) t = S - 1;
            cpa16(sb + SC_B0 + r * 128 + ((g ^ (r & 7)) << 4), krow + (size_t)t * D_TOT + d0 + g * 8);
        }
        CP_COMMIT();
    }

    for (int step = 0; step < KSTEPS; step++) {
        int buf = step & 1;
        if (step + 1 < KSTEPS) {
            int d0 = d_base + (step + 1) * 64;
            uint32_t a_of = AOF[buf ^ 1], b_of = BOF[buf ^ 1];
            #pragma unroll
            for (int j = 0; j < 4; j++) {
                int idx = tid + 256 * j, r = idx >> 3, g = idx & 7;
                int s = s0 + r; if (s >= S) s = S - 1;
                cpa16(sb + a_of + r * 128 + ((g ^ (r & 7)) << 4), qrow + (size_t)s * D_TOT + d0 + g * 8);
            }
            #pragma unroll
            for (int j = 0; j < 4; j++) {
                int idx = tid + 256 * j, r = idx >> 3, g = idx & 7;
                int t = t0 + r; if (t >= S) t = S - 1;
                cpa16(sb + b_of + r * 128 + ((g ^ (r & 7)) << 4), krow + (size_t)t * D_TOT + d0 + g * 8);
            }
            CP_COMMIT();
            CP_WAIT1();
        } else {
            CP_WAIT0();
        }
        __syncthreads();
        uint32_t Ab = sb + AOF[buf], Bb = sb + BOF[buf];
        #pragma unroll
        for (int kk = 0; kk < 4; kk++) {
            uint32_t af[4][4], bfr[2][4];
            #pragma unroll
            for (int f = 0; f < 4; f++) {
                int rowA = wm * 64 + f * 16 + (l & 15);
                int g = 2 * kk + (l >> 4);
                ldm4(af[f], Ab + rowA * 128 + ((g ^ (l & 7)) << 4));
            }
            #pragma unroll
            for (int h = 0; h < 2; h++) {
                int rowB = wn * 32 + h * 16 + (l & 7) + ((l >> 4) << 3);
                int g = 2 * kk + ((l >> 3) & 1);
                ldm4(bfr[h], Bb + rowB * 128 + ((g ^ (rowB & 7)) << 4));
            }
            #pragma unroll
            for (int f = 0; f < 4; f++)
                #pragma unroll
                for (int nf = 0; nf < 4; nf++)
                    mma_f16(acc[f][nf], af[f], &bfr[nf >> 1][(nf & 1) * 2]);
        }
        __syncthreads();
    }

    // epilogue: apply rq*rk, store split partials
    float* outp = g_attp + (size_t)split * (B * S * S) + (size_t)b * S * S;
    #pragma unroll
    for (int f = 0; f < 4; f++) {
        int r0 = s0 + wm * 64 + f * 16 + (l >> 2);
        #pragma unroll
        for (int half = 0; half < 2; half++) {
            int s = r0 + half * 8;
            if (s < S) {
                float rq = __ldg(&g_rq[b * S + s]);
                #pragma unroll
                for (int nf = 0; nf < 4; nf++) {
                    int t = t0 + wn * 32 + nf * 8 + (l & 3) * 2;
                    if (t < S) {
                        float2 o;
                        o.x = acc[f][nf][half * 2 + 0] * rq * __ldg(&g_rk[b * S + t]);
                        o.y = acc[f][nf][half * 2 + 1] * rq * __ldg(&g_rk[b * S + t + 1]);
                        *(float2*)(outp + (size_t)s * S + t) = o;
                    }
                }
            }
        }
    }
}

// ---------------------------------------------------------------------------
// K3: split-K reduce + causal softmax -> f16 probabilities.
// grid B*S, 320 threads.
// ---------------------------------------------------------------------------
__global__ __launch_bounds__(S) void softmax_kernel() {
    int row = blockIdx.x;
    int s = row % S;
    int tid = threadIdx.x;
    __shared__ float red[10];

    float x;
    if (tid <= s) {
        x = 0.f;
        #pragma unroll
        for (int sp = 0; sp < SK; sp++)
            x += g_attp[(size_t)sp * (B * S * S) + (size_t)row * S + tid];
    } else {
        x = -1e30f;
    }
    float m = x;
    #pragma unroll
    for (int o = 16; o; o >>= 1) m = fmaxf(m, __shfl_xor_sync(0xffffffffu, m, o));
    if ((tid & 31) == 0) red[tid >> 5] = m;
    __syncthreads();
    float mall = red[0];
    #pragma unroll
    for (int i = 1; i < 10; i++) mall = fmaxf(mall, red[i]);

    float e = (tid <= s) ? expf(x - mall) : 0.f;
    float ssum = e;
    #pragma unroll
    for (int o = 16; o; o >>= 1) ssum += __shfl_xor_sync(0xffffffffu, ssum, o);
    __syncthreads();
    if ((tid & 31) == 0) red[tid >> 5] = ssum;
    __syncthreads();
    float tot = 0.f;
    #pragma unroll
    for (int i = 0; i < 10; i++) tot += red[i];

    g_attb[(size_t)row * S + tid] = __float2half(e / tot);
}

// ---------------------------------------------------------------------------
// K4: out = att @ V + residual via mma.sync f16.  Tile M=64(s) x N=128(d),
// K = t-blocks of 64 (causal: stile+1 blocks).  2-stage, 48KB smem -> 4 CTAs/SM.
// grid (160, 5, B), 256 threads.
// ---------------------------------------------------------------------------
#define OU_A0 0
#define OU_A1 8192
#define OU_B0 16384
#define OU_B1 32768
#define OU_SMEM 49152

__global__ __launch_bounds__(256) void out_mma(const float* __restrict__ v,
                                               float* __restrict__ out) {
    extern __shared__ char sm[];
    uint32_t sb = smem_u32(sm);
    int ckp = blockIdx.x, stile = blockIdx.y, b = blockIdx.z;
    int s0 = stile * 64, n0 = ckp * 128;
    int tid = threadIdx.x, l = tid & 31, wid = tid >> 5;
    int wm = wid >> 2, wn = wid & 3;    // warp grid 2 (M: 32 rows) x 4 (N: 32 cols)
    int nblocks = stile + 1;

    const __half* pb = g_attb + (size_t)b * S * S;
    const __half* vb = g_vb + (size_t)b * S * D_TOT;

    float acc[2][4][4];
    #pragma unroll
    for (int f = 0; f < 2; f++)
        #pragma unroll
        for (int nf = 0; nf < 4; nf++)
            #pragma unroll
            for (int e = 0; e < 4; e++) acc[f][nf][e] = 0.f;

    const uint32_t AOF[2] = {OU_A0, OU_A1}, BOF[2] = {OU_B0, OU_B1};

    // fill block 0: A = att tile 64x64 (128B rows), B = V tile 64x128 (256B rows)
    {
        #pragma unroll
        for (int j = 0; j < 2; j++) {
            int idx = tid + 256 * j, r = idx >> 3, g = idx & 7;
            cpa16(sb + OU_A0 + r * 128 + ((g ^ (r & 7)) << 4), pb + (size_t)(s0 + r) * S + g * 8);
        }
        #pragma unroll
        for (int j = 0; j < 4; j++) {
            int idx = tid + 256 * j, r = idx >> 4, g = idx & 15;
            cpa16(sb + OU_B0 + r * 256 + ((g ^ (r & 7)) << 4), vb + (size_t)r * D_TOT + n0 + g * 8);
        }
        CP_COMMIT();
    }

    for (int tt = 0; tt < nblocks; tt++) {
        int buf = tt & 1;
        if (tt + 1 < nblocks) {
            int t1 = (tt + 1) * 64;
            uint32_t a_of = AOF[buf ^ 1], b_of = BOF[buf ^ 1];
            #pragma unroll
            for (int j = 0; j < 2; j++) {
                int idx = tid + 256 * j, r = idx >> 3, g = idx & 7;
                cpa16(sb + a_of + r * 128 + ((g ^ (r & 7)) << 4), pb + (size_t)(s0 + r) * S + t1 + g * 8);
            }
            #pragma unroll
            for (int j = 0; j < 4; j++) {
                int idx = tid + 256 * j, r = idx >> 4, g = idx & 15;
                cpa16(sb + b_of + r * 256 + ((g ^ (r & 7)) << 4), vb + (size_t)(t1 + r) * D_TOT + n0 + g * 8);
            }
            CP_COMMIT();
            CP_WAIT1();
        } else {
            CP_WAIT0();
        }
        __syncthreads();
        uint32_t Ab = sb + AOF[buf], Bb = sb + BOF[buf];
        #pragma unroll
        for (int kk = 0; kk < 4; kk++) {
            uint32_t af[2][4], bfr[2][4];
            #pragma unroll
            for (int f = 0; f < 2; f++) {
                int rowA = wm * 32 + f * 16 + (l & 15);
                int g = 2 * kk + (l >> 4);
                ldm4(af[f], Ab + rowA * 128 + ((g ^ (l & 7)) << 4));
            }
            #pragma unroll
            for (int h = 0; h < 2; h++) {
                int rowB = kk * 16 + (l & 15);
                int g = wn * 4 + h * 2 + (l >> 4);
                ldm4t(bfr[h], Bb + rowB * 256 + ((g ^ (rowB & 7)) << 4));
            }
            #pragma unroll
            for (int f = 0; f < 2; f++)
                #pragma unroll
                for (int nf = 0; nf < 4; nf++)
                    mma_f16(acc[f][nf], af[f], &bfr[nf >> 1][(nf & 1) * 2]);
        }
        __syncthreads();
    }

    // epilogue: residual add (fp32 token_v) + store to original layout
    #pragma unroll
    for (int f = 0; f < 2; f++) {
        #pragma unroll
        for (int half = 0; half < 2; half++) {
            int s = s0 + wm * 32 + f * 16 + (l >> 2) + half * 8;
            #pragma unroll
            for (int nf = 0; nf < 4; nf++) {
                int d = n0 + wn * 32 + nf * 8 + (l & 3) * 2;
                int ck = d >> 6, w = d & 63;
                size_t g = elem_base(b, s, ck) + w;
                float2 vv = *(const float2*)(v + g);
                float2 o;
                o.x = acc[f][nf][half * 2 + 0] + vv.x;
                o.y = acc[f][nf][half * 2 + 1] + vv.y;
                *(float2*)(out + g) = o;
            }
        }
    }
}

// ---------------------------------------------------------------------------
extern "C" void kernel_launch(void* const* d_in, const int* in_sizes, int n_in,
                              void* d_out, int out_size) {
    const float* q = (const float*)d_in[0];
    const float* k = (const float*)d_in[1];
    const float* v = (const float*)d_in[2];
    float* out = (float*)d_out;

    static bool attr_done = false;
    if (!attr_done) {
        cudaFuncSetAttribute(scores_mma, cudaFuncAttributeMaxDynamicSharedMemorySize, SC_SMEM);
        cudaFuncSetAttribute(out_mma, cudaFuncAttributeMaxDynamicSharedMemorySize, OU_SMEM);
        attr_done = true;
    }

    convnorm_kernel<<<dim3(B * S, 3), 256>>>(q, k, v);
    scores_mma<<<dim3(6, SK, B), 256, SC_SMEM>>>();
    softmax_kernel<<<B * S, S>>>();
    out_mma<<<dim3(160, 5, B), 256, OU_SMEM>>>(v, out);
}

// round 14
// speedup vs baseline: 1.4422x; 1.0901x over previous
#include <cuda_runtime.h>
#include <cuda_fp16.h>
#include <math.h>
#include <cstdint>

// Problem constants
#define B 4
#define C 64
#define NA 25
#define H 64
#define W 64
#define S 320        // H*U
#define NCHUNK 320   // chunks of 64 floats along w
#define D_TOT 20480  // feature dim
#define BSTRIDE 6553600
#define CSTRIDE 102400
#define NSTRIDE 4096
#define SK 16                       // split-K for scores
#define KSTEPS (D_TOT / SK / 64)    // 20 K-blocks of 64 per split

typedef unsigned long long u64;

// ---- scratch (device globals; no allocations allowed) ----
__device__ float g_rq[B * S];
__device__ float g_rk[B * S];
__device__ float g_attp[(size_t)SK * B * S * S];   // split-K partial scores (f32)
__device__ __half g_attb[(size_t)B * S * S];       // softmax probs (f16)
__device__ __half g_qb[(size_t)B * S * D_TOT];
__device__ __half g_kb[(size_t)B * S * D_TOT];
__device__ __half g_vb[(size_t)B * S * D_TOT];

// original-layout address of (b, s, chunk ck, w=0)
__device__ __forceinline__ size_t elem_base(int b, int s, int ck) {
    int h = s / 5, uu = s - h * 5;
    int c = ck / 5, vv = ck - c * 5;
    return (size_t)b * BSTRIDE + (size_t)c * CSTRIDE + (size_t)(uu * 5 + vv) * NSTRIDE + (size_t)h * W;
}

// ---- PTX helpers (sm_80-level: valid at virtual target sm_103) ----
__device__ __forceinline__ uint32_t smem_u32(const void* p) {
    uint32_t a;
    asm("{ .reg .u64 t; cvta.to.shared.u64 t, %1; cvt.u32.u64 %0, t; }" : "=r"(a) : "l"(p));
    return a;
}
__device__ __forceinline__ void cpa16(uint32_t dst, const void* src) {
    asm volatile("{ .reg .u64 g; cvta.to.global.u64 g, %1; cp.async.cg.shared.global [%0], [g], 16; }"
                 :: "r"(dst), "l"(src) : "memory");
}
#define CP_COMMIT() asm volatile("cp.async.commit_group;" ::: "memory")
#define CP_WAIT0()  asm volatile("cp.async.wait_group 0;" ::: "memory")
#define CP_WAIT1()  asm volatile("cp.async.wait_group 1;" ::: "memory")

__device__ __forceinline__ void ldm4(uint32_t* r, uint32_t addr) {
    asm volatile("ldmatrix.sync.aligned.m8n8.x4.shared.b16 {%0,%1,%2,%3}, [%4];"
                 : "=r"(r[0]), "=r"(r[1]), "=r"(r[2]), "=r"(r[3]) : "r"(addr));
}
__device__ __forceinline__ void ldm4t(uint32_t* r, uint32_t addr) {
    asm volatile("ldmatrix.sync.aligned.m8n8.x4.trans.shared.b16 {%0,%1,%2,%3}, [%4];"
                 : "=r"(r[0]), "=r"(r[1]), "=r"(r[2]), "=r"(r[3]) : "r"(addr));
}
__device__ __forceinline__ void mma_f16(float* d, const uint32_t* a, const uint32_t* b) {
    asm volatile("mma.sync.aligned.m16n8k16.row.col.f32.f16.f16.f32 "
                 "{%0,%1,%2,%3}, {%4,%5,%6,%7}, {%8,%9}, {%0,%1,%2,%3};"
                 : "+f"(d[0]), "+f"(d[1]), "+f"(d[2]), "+f"(d[3])
                 : "r"(a[0]), "r"(a[1]), "r"(a[2]), "r"(a[3]), "r"(b[0]), "r"(b[1]));
}

// pack 8 f32 -> 8 f16 in a uint4
__device__ __forceinline__ uint4 pack8(float4 x0, float4 x1) {
    uint4 wv;
    __half2 p0 = __floats2half2_rn(x0.x, x0.y);
    __half2 p1 = __floats2half2_rn(x0.z, x0.w);
    __half2 p2 = __floats2half2_rn(x1.x, x1.y);
    __half2 p3 = __floats2half2_rn(x1.z, x1.w);
    *reinterpret_cast<__half2*>(&wv.x) = p0;
    *reinterpret_cast<__half2*>(&wv.y) = p1;
    *reinterpret_cast<__half2*>(&wv.z) = p2;
    *reinterpret_cast<__half2*>(&wv.w) = p3;
    return wv;
}

// ---------------------------------------------------------------------------
// K1: fused gather + f16 convert (Q, K, V) + row inverse-norms (Q, K).
// grid (B*S, 3), 256 threads.  8 floats/thread/iter (2 independent LDG.128).
// ---------------------------------------------------------------------------
__global__ __launch_bounds__(256) void convnorm_kernel(const float* __restrict__ q,
                                                       const float* __restrict__ k,
                                                       const float* __restrict__ v) {
    int row = blockIdx.x;
    int which = blockIdx.y;
    const float* src = (which == 0) ? q : (which == 1) ? k : v;
    __half* dstb = (which == 0) ? g_qb : (which == 1) ? g_kb : g_vb;
    int b = row / S, s = row - b * S;

    uint4* drow = (uint4*)(dstb + (size_t)row * D_TOT);
    float acc = 0.f;
    #pragma unroll 2
    for (int i = threadIdx.x; i < NCHUNK * 8; i += 256) {
        int ck = i >> 3, f8 = i & 7;
        const float* base = src + elem_base(b, s, ck) + f8 * 8;
        float4 x0 = *(const float4*)base;
        float4 x1 = *(const float4*)(base + 4);
        acc += x0.x * x0.x + x0.y * x0.y + x0.z * x0.z + x0.w * x0.w
             + x1.x * x1.x + x1.y * x1.y + x1.z * x1.z + x1.w * x1.w;
        drow[i] = pack8(x0, x1);
    }
    if (which < 2) {
        __shared__ float red[256];
        red[threadIdx.x] = acc;
        __syncthreads();
        for (int off = 128; off; off >>= 1) {
            if (threadIdx.x < off) red[threadIdx.x] += red[threadIdx.x + off];
            __syncthreads();
        }
        if (threadIdx.x == 0)
            (which ? g_rk : g_rq)[row] = 1.f / fmaxf(sqrtf(red[0]), 1e-12f);
    }
}

// ---------------------------------------------------------------------------
// K2: scores = Q K^T via mma.sync f16.  Tile 128x128, K-blocks of 64,
// split-K=16.  cp.async double buffer, XOR-swizzled smem, causal tile list.
// grid (6 pairs, 16 splits, B), 256 threads, 64KB dynamic smem.
// ---------------------------------------------------------------------------
#define SC_A0 0
#define SC_A1 16384
#define SC_B0 32768
#define SC_B1 49152
#define SC_SMEM 65536

__global__ __launch_bounds__(256) void scores_mma() {
    extern __shared__ char sm[];
    uint32_t sb = smem_u32(sm);
    const int MI[6] = {0, 1, 1, 2, 2, 2};
    const int NJ[6] = {0, 0, 1, 0, 1, 2};
    int pair = blockIdx.x, split = blockIdx.y, b = blockIdx.z;
    int s0 = MI[pair] * 128, t0 = NJ[pair] * 128;
    int tid = threadIdx.x, l = tid & 31, wid = tid >> 5;
    int wm = wid >> 2, wn = wid & 3;    // warp grid 2 (M) x 4 (N)
    int d_base = split * (D_TOT / SK);

    const __half* qrow = g_qb + (size_t)b * S * D_TOT;
    const __half* krow = g_kb + (size_t)b * S * D_TOT;

    float acc[4][4][4];
    #pragma unroll
    for (int f = 0; f < 4; f++)
        #pragma unroll
        for (int nf = 0; nf < 4; nf++)
            #pragma unroll
            for (int e = 0; e < 4; e++) acc[f][nf][e] = 0.f;

    const uint32_t AOF[2] = {SC_A0, SC_A1}, BOF[2] = {SC_B0, SC_B1};

    // fill step 0
    {
        int d0 = d_base;
        #pragma unroll
        for (int j = 0; j < 4; j++) {
            int idx = tid + 256 * j, r = idx >> 3, g = idx & 7;
            int s = s0 + r; if (s >= S) s = S - 1;
            cpa16(sb + SC_A0 + r * 128 + ((g ^ (r & 7)) << 4), qrow + (size_t)s * D_TOT + d0 + g * 8);
        }
        #pragma unroll
        for (int j = 0; j < 4; j++) {
            int idx = tid + 256 * j, r = idx >> 3, g = idx & 7;
            int t = t0 + r; if (t >= S) t = S - 1;
            cpa16(sb + SC_B0 + r * 128 + ((g ^ (r & 7)) << 4), krow + (size_t)t * D_TOT + d0 + g * 8);
        }
        CP_COMMIT();
    }

    for (int step = 0; step < KSTEPS; step++) {
        int buf = step & 1;
        if (step + 1 < KSTEPS) {
            int d0 = d_base + (step + 1) * 64;
            uint32_t a_of = AOF[buf ^ 1], b_of = BOF[buf ^ 1];
            #pragma unroll
            for (int j = 0; j < 4; j++) {
                int idx = tid + 256 * j, r = idx >> 3, g = idx & 7;
                int s = s0 + r; if (s >= S) s = S - 1;
                cpa16(sb + a_of + r * 128 + ((g ^ (r & 7)) << 4), qrow + (size_t)s * D_TOT + d0 + g * 8);
            }
            #pragma unroll
            for (int j = 0; j < 4; j++) {
                int idx = tid + 256 * j, r = idx >> 3, g = idx & 7;
                int t = t0 + r; if (t >= S) t = S - 1;
                cpa16(sb + b_of + r * 128 + ((g ^ (r & 7)) << 4), krow + (size_t)t * D_TOT + d0 + g * 8);
            }
            CP_COMMIT();
            CP_WAIT1();
        } else {
            CP_WAIT0();
        }
        __syncthreads();
        uint32_t Ab = sb + AOF[buf], Bb = sb + BOF[buf];
        #pragma unroll
        for (int kk = 0; kk < 4; kk++) {
            uint32_t af[4][4], bfr[2][4];
            #pragma unroll
            for (int f = 0; f < 4; f++) {
                int rowA = wm * 64 + f * 16 + (l & 15);
                int g = 2 * kk + (l >> 4);
                ldm4(af[f], Ab + rowA * 128 + ((g ^ (l & 7)) << 4));
            }
            #pragma unroll
            for (int h = 0; h < 2; h++) {
                int rowB = wn * 32 + h * 16 + (l & 7) + ((l >> 4) << 3);
                int g = 2 * kk + ((l >> 3) & 1);
                ldm4(bfr[h], Bb + rowB * 128 + ((g ^ (rowB & 7)) << 4));
            }
            #pragma unroll
            for (int f = 0; f < 4; f++)
                #pragma unroll
                for (int nf = 0; nf < 4; nf++)
                    mma_f16(acc[f][nf], af[f], &bfr[nf >> 1][(nf & 1) * 2]);
        }
        __syncthreads();
    }

    // epilogue: apply rq*rk, store split partials
    float* outp = g_attp + (size_t)split * (B * S * S) + (size_t)b * S * S;
    #pragma unroll
    for (int f = 0; f < 4; f++) {
        int r0 = s0 + wm * 64 + f * 16 + (l >> 2);
        #pragma unroll
        for (int half = 0; half < 2; half++) {
            int s = r0 + half * 8;
            if (s < S) {
                float rq = __ldg(&g_rq[b * S + s]);
                #pragma unroll
                for (int nf = 0; nf < 4; nf++) {
                    int t = t0 + wn * 32 + nf * 8 + (l & 3) * 2;
                    if (t < S) {
                        float2 o;
                        o.x = acc[f][nf][half * 2 + 0] * rq * __ldg(&g_rk[b * S + t]);
                        o.y = acc[f][nf][half * 2 + 1] * rq * __ldg(&g_rk[b * S + t + 1]);
                        *(float2*)(outp + (size_t)s * S + t) = o;
                    }
                }
            }
        }
    }
}

// ---------------------------------------------------------------------------
// K3: split-K reduce + causal softmax -> f16 probabilities.
// grid B*S, 320 threads.
// ---------------------------------------------------------------------------
__global__ __launch_bounds__(S) void softmax_kernel() {
    int row = blockIdx.x;
    int s = row % S;
    int tid = threadIdx.x;
    __shared__ float red[10];

    float x;
    if (tid <= s) {
        x = 0.f;
        #pragma unroll
        for (int sp = 0; sp < SK; sp++)
            x += g_attp[(size_t)sp * (B * S * S) + (size_t)row * S + tid];
    } else {
        x = -1e30f;
    }
    float m = x;
    #pragma unroll
    for (int o = 16; o; o >>= 1) m = fmaxf(m, __shfl_xor_sync(0xffffffffu, m, o));
    if ((tid & 31) == 0) red[tid >> 5] = m;
    __syncthreads();
    float mall = red[0];
    #pragma unroll
    for (int i = 1; i < 10; i++) mall = fmaxf(mall, red[i]);

    float e = (tid <= s) ? expf(x - mall) : 0.f;
    float ssum = e;
    #pragma unroll
    for (int o = 16; o; o >>= 1) ssum += __shfl_xor_sync(0xffffffffu, ssum, o);
    __syncthreads();
    if ((tid & 31) == 0) red[tid >> 5] = ssum;
    __syncthreads();
    float tot = 0.f;
    #pragma unroll
    for (int i = 0; i < 10; i++) tot += red[i];

    g_attb[(size_t)row * S + tid] = __float2half(e / tot);
}

// ---------------------------------------------------------------------------
// K4: out = att @ V + residual via mma.sync f16.  Tile M=64(s) x N=128(d),
// K = t-blocks of 64 (causal: stile+1 blocks).  2-stage, 48KB smem -> 4 CTAs/SM.
// Epilogue stages acc through smem for fully-coalesced v-read/out-write.
// grid (160, 5, B), 256 threads.
// ---------------------------------------------------------------------------
#define OU_A0 0
#define OU_A1 8192
#define OU_B0 16384
#define OU_B1 32768
#define OU_SMEM 49152
#define STG_STRIDE 132   // fp32 staging row stride (spreads banks: 132*4 mod 128 != 0)

__global__ __launch_bounds__(256) void out_mma(const float* __restrict__ v,
                                               float* __restrict__ out) {
    extern __shared__ char sm[];
    uint32_t sb = smem_u32(sm);
    int ckp = blockIdx.x, stile = blockIdx.y, b = blockIdx.z;
    int s0 = stile * 64, n0 = ckp * 128;
    int tid = threadIdx.x, l = tid & 31, wid = tid >> 5;
    int wm = wid >> 2, wn = wid & 3;    // warp grid 2 (M: 32 rows) x 4 (N: 32 cols)
    int nblocks = stile + 1;

    const __half* pb = g_attb + (size_t)b * S * S;
    const __half* vb = g_vb + (size_t)b * S * D_TOT;

    float acc[2][4][4];
    #pragma unroll
    for (int f = 0; f < 2; f++)
        #pragma unroll
        for (int nf = 0; nf < 4; nf++)
            #pragma unroll
            for (int e = 0; e < 4; e++) acc[f][nf][e] = 0.f;

    const uint32_t AOF[2] = {OU_A0, OU_A1}, BOF[2] = {OU_B0, OU_B1};

    // fill block 0: A = att tile 64x64 (128B rows), B = V tile 64x128 (256B rows)
    {
        #pragma unroll
        for (int j = 0; j < 2; j++) {
            int idx = tid + 256 * j, r = idx >> 3, g = idx & 7;
            cpa16(sb + OU_A0 + r * 128 + ((g ^ (r & 7)) << 4), pb + (size_t)(s0 + r) * S + g * 8);
        }
        #pragma unroll
        for (int j = 0; j < 4; j++) {
            int idx = tid + 256 * j, r = idx >> 4, g = idx & 15;
            cpa16(sb + OU_B0 + r * 256 + ((g ^ (r & 7)) << 4), vb + (size_t)r * D_TOT + n0 + g * 8);
        }
        CP_COMMIT();
    }

    for (int tt = 0; tt < nblocks; tt++) {
        int buf = tt & 1;
        if (tt + 1 < nblocks) {
            int t1 = (tt + 1) * 64;
            uint32_t a_of = AOF[buf ^ 1], b_of = BOF[buf ^ 1];
            #pragma unroll
            for (int j = 0; j < 2; j++) {
                int idx = tid + 256 * j, r = idx >> 3, g = idx & 7;
                cpa16(sb + a_of + r * 128 + ((g ^ (r & 7)) << 4), pb + (size_t)(s0 + r) * S + t1 + g * 8);
            }
            #pragma unroll
            for (int j = 0; j < 4; j++) {
                int idx = tid + 256 * j, r = idx >> 4, g = idx & 15;
                cpa16(sb + b_of + r * 256 + ((g ^ (r & 7)) << 4), vb + (size_t)(t1 + r) * D_TOT + n0 + g * 8);
            }
            CP_COMMIT();
            CP_WAIT1();
        } else {
            CP_WAIT0();
        }
        __syncthreads();
        uint32_t Ab = sb + AOF[buf], Bb = sb + BOF[buf];
        #pragma unroll
        for (int kk = 0; kk < 4; kk++) {
            uint32_t af[2][4], bfr[2][4];
            #pragma unroll
            for (int f = 0; f < 2; f++) {
                int rowA = wm * 32 + f * 16 + (l & 15);
                int g = 2 * kk + (l >> 4);
                ldm4(af[f], Ab + rowA * 128 + ((g ^ (l & 7)) << 4));
            }
            #pragma unroll
            for (int h = 0; h < 2; h++) {
                int rowB = kk * 16 + (l & 15);
                int g = wn * 4 + h * 2 + (l >> 4);
                ldm4t(bfr[h], Bb + rowB * 256 + ((g ^ (rowB & 7)) << 4));
            }
            #pragma unroll
            for (int f = 0; f < 2; f++)
                #pragma unroll
                for (int nf = 0; nf < 4; nf++)
                    mma_f16(acc[f][nf], af[f], &bfr[nf >> 1][(nf & 1) * 2]);
        }
        __syncthreads();
    }

    // ---- epilogue: stage acc -> smem, then coalesced residual+store ----
    float* stage = (float*)sm;   // 64 x STG_STRIDE fp32 = 33792 B (smem free now)
    #pragma unroll
    for (int f = 0; f < 2; f++) {
        #pragma unroll
        for (int half = 0; half < 2; half++) {
            int r = wm * 32 + f * 16 + (l >> 2) + half * 8;   // 0..63
            #pragma unroll
            for (int nf = 0; nf < 4; nf++) {
                int col = wn * 32 + nf * 8 + (l & 3) * 2;
                stage[r * STG_STRIDE + col]     = acc[f][nf][half * 2 + 0];
                stage[r * STG_STRIDE + col + 1] = acc[f][nf][half * 2 + 1];
            }
        }
    }
    __syncthreads();
    // block-wide coalesced copy: 64 rows x 128 floats = 2048 float4
    #pragma unroll
    for (int j = 0; j < 8; j++) {
        int idx = tid + 256 * j;
        int r = idx >> 5, pos = idx & 31;      // pos: float4 index within row
        int d = pos * 4;                        // 0..124
        int ck = ckp * 2 + (d >> 6), w = d & 63;
        size_t g = elem_base(b, s0 + r, ck) + w;
        float4 a = *(const float4*)&stage[r * STG_STRIDE + d];
        float4 vv = *(const float4*)(v + g);
        float4 o;
        o.x = a.x + vv.x;
        o.y = a.y + vv.y;
        o.z = a.z + vv.z;
        o.w = a.w + vv.w;
        *(float4*)(out + g) = o;
    }
}

// ---------------------------------------------------------------------------
extern "C" void kernel_launch(void* const* d_in, const int* in_sizes, int n_in,
                              void* d_out, int out_size) {
    const float* q = (const float*)d_in[0];
    const float* k = (const float*)d_in[1];
    const float* v = (const float*)d_in[2];
    float* out = (float*)d_out;

    static bool attr_done = false;
    if (!attr_done) {
        cudaFuncSetAttribute(scores_mma, cudaFuncAttributeMaxDynamicSharedMemorySize, SC_SMEM);
        cudaFuncSetAttribute(out_mma, cudaFuncAttributeMaxDynamicSharedMemorySize, OU_SMEM);
        attr_done = true;
    }

    convnorm_kernel<<<dim3(B * S, 3), 256>>>(q, k, v);
    scores_mma<<<dim3(6, SK, B), 256, SC_SMEM>>>();
    softmax_kernel<<<B * S, S>>>();
    out_mma<<<dim3(160, 5, B), 256, OU_SMEM>>>(v, out);
}

// round 15
// speedup vs baseline: 1.5180x; 1.0526x over previous
#include <cuda_runtime.h>
#include <cuda_fp16.h>
#include <math.h>
#include <cstdint>

// Problem constants
#define B 4
#define C 64
#define NA 25
#define H 64
#define W 64
#define S 320        // H*U
#define NCHUNK 320   // chunks of 64 floats along w
#define D_TOT 20480  // feature dim
#define BSTRIDE 6553600
#define CSTRIDE 102400
#define NSTRIDE 4096
#define SK 16                       // split-K for scores
#define KSTEPS (D_TOT / SK / 64)    // 20 K-blocks of 64 per split

typedef unsigned long long u64;

// ---- scratch (device globals; no allocations allowed) ----
__device__ float g_rq[B * S];
__device__ float g_rk[B * S];
__device__ float g_attp[(size_t)SK * B * S * S];   // split-K partial scores (f32)
__device__ __half g_attb[(size_t)B * S * S];       // softmax probs (f16)
__device__ __half g_qb[(size_t)B * S * D_TOT];
__device__ __half g_kb[(size_t)B * S * D_TOT];
__device__ __half g_vb[(size_t)B * S * D_TOT];

// original-layout address of (b, s, chunk ck, w=0)
__device__ __forceinline__ size_t elem_base(int b, int s, int ck) {
    int h = s / 5, uu = s - h * 5;
    int c = ck / 5, vv = ck - c * 5;
    return (size_t)b * BSTRIDE + (size_t)c * CSTRIDE + (size_t)(uu * 5 + vv) * NSTRIDE + (size_t)h * W;
}

// ---- PTX helpers (sm_80-level: valid at virtual target sm_103) ----
__device__ __forceinline__ uint32_t smem_u32(const void* p) {
    uint32_t a;
    asm("{ .reg .u64 t; cvta.to.shared.u64 t, %1; cvt.u32.u64 %0, t; }" : "=r"(a) : "l"(p));
    return a;
}
__device__ __forceinline__ void cpa16(uint32_t dst, const void* src) {
    asm volatile("{ .reg .u64 g; cvta.to.global.u64 g, %1; cp.async.cg.shared.global [%0], [g], 16; }"
                 :: "r"(dst), "l"(src) : "memory");
}
#define CP_COMMIT() asm volatile("cp.async.commit_group;" ::: "memory")
#define CP_WAIT0()  asm volatile("cp.async.wait_group 0;" ::: "memory")
#define CP_WAIT1()  asm volatile("cp.async.wait_group 1;" ::: "memory")

__device__ __forceinline__ void ldm4(uint32_t* r, uint32_t addr) {
    asm volatile("ldmatrix.sync.aligned.m8n8.x4.shared.b16 {%0,%1,%2,%3}, [%4];"
                 : "=r"(r[0]), "=r"(r[1]), "=r"(r[2]), "=r"(r[3]) : "r"(addr));
}
__device__ __forceinline__ void ldm4t(uint32_t* r, uint32_t addr) {
    asm volatile("ldmatrix.sync.aligned.m8n8.x4.trans.shared.b16 {%0,%1,%2,%3}, [%4];"
                 : "=r"(r[0]), "=r"(r[1]), "=r"(r[2]), "=r"(r[3]) : "r"(addr));
}
__device__ __forceinline__ void mma_f16(float* d, const uint32_t* a, const uint32_t* b) {
    asm volatile("mma.sync.aligned.m16n8k16.row.col.f32.f16.f16.f32 "
                 "{%0,%1,%2,%3}, {%4,%5,%6,%7}, {%8,%9}, {%0,%1,%2,%3};"
                 : "+f"(d[0]), "+f"(d[1]), "+f"(d[2]), "+f"(d[3])
                 : "r"(a[0]), "r"(a[1]), "r"(a[2]), "r"(a[3]), "r"(b[0]), "r"(b[1]));
}

// pack 8 f32 -> 8 f16 in a uint4
__device__ __forceinline__ uint4 pack8(float4 x0, float4 x1) {
    uint4 wv;
    __half2 p0 = __floats2half2_rn(x0.x, x0.y);
    __half2 p1 = __floats2half2_rn(x0.z, x0.w);
    __half2 p2 = __floats2half2_rn(x1.x, x1.y);
    __half2 p3 = __floats2half2_rn(x1.z, x1.w);
    *reinterpret_cast<__half2*>(&wv.x) = p0;
    *reinterpret_cast<__half2*>(&wv.y) = p1;
    *reinterpret_cast<__half2*>(&wv.z) = p2;
    *reinterpret_cast<__half2*>(&wv.w) = p3;
    return wv;
}

// ---------------------------------------------------------------------------
// K1: fused gather + f16 convert (Q, K, V) + row inverse-norms (Q, K).
// grid (B*S, 3), 256 threads.  16 floats/thread/iter (4 independent LDG.128).
// ---------------------------------------------------------------------------
__global__ __launch_bounds__(256) void convnorm_kernel(const float* __restrict__ q,
                                                       const float* __restrict__ k,
                                                       const float* __restrict__ v) {
    int row = blockIdx.x;
    int which = blockIdx.y;
    const float* src = (which == 0) ? q : (which == 1) ? k : v;
    __half* dstb = (which == 0) ? g_qb : (which == 1) ? g_kb : g_vb;
    int b = row / S, s = row - b * S;

    uint4* drow = (uint4*)(dstb + (size_t)row * D_TOT);
    float acc = 0.f;
    for (int i = threadIdx.x; i < NCHUNK * 4; i += 256) {
        int ck = i >> 2, q16 = i & 3;
        const float* base = src + elem_base(b, s, ck) + q16 * 16;
        float4 x0 = *(const float4*)base;
        float4 x1 = *(const float4*)(base + 4);
        float4 x2 = *(const float4*)(base + 8);
        float4 x3 = *(const float4*)(base + 12);
        acc += x0.x * x0.x + x0.y * x0.y + x0.z * x0.z + x0.w * x0.w
             + x1.x * x1.x + x1.y * x1.y + x1.z * x1.z + x1.w * x1.w
             + x2.x * x2.x + x2.y * x2.y + x2.z * x2.z + x2.w * x2.w
             + x3.x * x3.x + x3.y * x3.y + x3.z * x3.z + x3.w * x3.w;
        drow[2 * i]     = pack8(x0, x1);
        drow[2 * i + 1] = pack8(x2, x3);
    }
    if (which < 2) {
        __shared__ float red[256];
        red[threadIdx.x] = acc;
        __syncthreads();
        for (int off = 128; off; off >>= 1) {
            if (threadIdx.x < off) red[threadIdx.x] += red[threadIdx.x + off];
            __syncthreads();
        }
        if (threadIdx.x == 0)
            (which ? g_rk : g_rq)[row] = 1.f / fmaxf(sqrtf(red[0]), 1e-12f);
    }
}

// ---------------------------------------------------------------------------
// K2: scores = Q K^T via mma.sync f16.  Tile M=64 x N=128 (causal 9-tile list:
// 25% fewer MACs than 128x128 pairing; t>s entries unused by softmax).
// K-blocks of 64, split-K=16.  cp.async double buffer, XOR-swizzled smem.
// grid (9 tiles, 16 splits, B), 256 threads, 48KB dynamic smem -> 4 CTAs/SM.
// ---------------------------------------------------------------------------
#define SC_A0 0
#define SC_A1 8192
#define SC_B0 16384
#define SC_B1 32768
#define SC_SMEM 49152

__global__ __launch_bounds__(256) void scores_mma() {
    extern __shared__ char sm[];
    uint32_t sb = smem_u32(sm);
    const int MI[9] = {0, 1, 2, 2, 3, 3, 4, 4, 4};
    const int NJ[9] = {0, 0, 0, 1, 0, 1, 0, 1, 2};
    int tile = blockIdx.x, split = blockIdx.y, b = blockIdx.z;
    int s0 = MI[tile] * 64, t0 = NJ[tile] * 128;
    int tid = threadIdx.x, l = tid & 31, wid = tid >> 5;
    int wm = wid >> 2, wn = wid & 3;    // warp grid 2 (M: 32 rows) x 4 (N: 32 cols)
    int d_base = split * (D_TOT / SK);

    const __half* qrow = g_qb + (size_t)b * S * D_TOT;
    const __half* krow = g_kb + (size_t)b * S * D_TOT;

    float acc[2][4][4];
    #pragma unroll
    for (int f = 0; f < 2; f++)
        #pragma unroll
        for (int nf = 0; nf < 4; nf++)
            #pragma unroll
            for (int e = 0; e < 4; e++) acc[f][nf][e] = 0.f;

    const uint32_t AOF[2] = {SC_A0, SC_A1}, BOF[2] = {SC_B0, SC_B1};

    // fill step 0: A = 64x64 f16 (128B rows), B = 128x64 f16 (128B rows)
    {
        int d0 = d_base;
        #pragma unroll
        for (int j = 0; j < 2; j++) {
            int idx = tid + 256 * j, r = idx >> 3, g = idx & 7;
            cpa16(sb + SC_A0 + r * 128 + ((g ^ (r & 7)) << 4), qrow + (size_t)(s0 + r) * D_TOT + d0 + g * 8);
        }
        #pragma unroll
        for (int j = 0; j < 4; j++) {
            int idx = tid + 256 * j, r = idx >> 3, g = idx & 7;
            int t = t0 + r; if (t >= S) t = S - 1;
            cpa16(sb + SC_B0 + r * 128 + ((g ^ (r & 7)) << 4), krow + (size_t)t * D_TOT + d0 + g * 8);
        }
        CP_COMMIT();
    }

    for (int step = 0; step < KSTEPS; step++) {
        int buf = step & 1;
        if (step + 1 < KSTEPS) {
            int d0 = d_base + (step + 1) * 64;
            uint32_t a_of = AOF[buf ^ 1], b_of = BOF[buf ^ 1];
            #pragma unroll
            for (int j = 0; j < 2; j++) {
                int idx = tid + 256 * j, r = idx >> 3, g = idx & 7;
                cpa16(sb + a_of + r * 128 + ((g ^ (r & 7)) << 4), qrow + (size_t)(s0 + r) * D_TOT + d0 + g * 8);
            }
            #pragma unroll
            for (int j = 0; j < 4; j++) {
                int idx = tid + 256 * j, r = idx >> 3, g = idx & 7;
                int t = t0 + r; if (t >= S) t = S - 1;
                cpa16(sb + b_of + r * 128 + ((g ^ (r & 7)) << 4), krow + (size_t)t * D_TOT + d0 + g * 8);
            }
            CP_COMMIT();
            CP_WAIT1();
        } else {
            CP_WAIT0();
        }
        __syncthreads();
        uint32_t Ab = sb + AOF[buf], Bb = sb + BOF[buf];
        #pragma unroll
        for (int kk = 0; kk < 4; kk++) {
            uint32_t af[2][4], bfr[2][4];
            #pragma unroll
            for (int f = 0; f < 2; f++) {
                int rowA = wm * 32 + f * 16 + (l & 15);
                int g = 2 * kk + (l >> 4);
                ldm4(af[f], Ab + rowA * 128 + ((g ^ (l & 7)) << 4));
            }
            #pragma unroll
            for (int h = 0; h < 2; h++) {
                int rowB = wn * 32 + h * 16 + (l & 7) + ((l >> 4) << 3);
                int g = 2 * kk + ((l >> 3) & 1);
                ldm4(bfr[h], Bb + rowB * 128 + ((g ^ (rowB & 7)) << 4));
            }
            #pragma unroll
            for (int f = 0; f < 2; f++)
                #pragma unroll
                for (int nf = 0; nf < 4; nf++)
                    mma_f16(acc[f][nf], af[f], &bfr[nf >> 1][(nf & 1) * 2]);
        }
        __syncthreads();
    }

    // epilogue: apply rq*rk, store split partials
    float* outp = g_attp + (size_t)split * (B * S * S) + (size_t)b * S * S;
    #pragma unroll
    for (int f = 0; f < 2; f++) {
        int r0 = s0 + wm * 32 + f * 16 + (l >> 2);
        #pragma unroll
        for (int half = 0; half < 2; half++) {
            int s = r0 + half * 8;
            float rq = __ldg(&g_rq[b * S + s]);
            #pragma unroll
            for (int nf = 0; nf < 4; nf++) {
                int t = t0 + wn * 32 + nf * 8 + (l & 3) * 2;
                if (t < S) {
                    float2 o;
                    o.x = acc[f][nf][half * 2 + 0] * rq * __ldg(&g_rk[b * S + t]);
                    o.y = acc[f][nf][half * 2 + 1] * rq * __ldg(&g_rk[b * S + t + 1]);
                    *(float2*)(outp + (size_t)s * S + t) = o;
                }
            }
        }
    }
}

// ---------------------------------------------------------------------------
// K3: split-K reduce + causal softmax -> f16 probabilities.
// grid B*S, 320 threads.
// ---------------------------------------------------------------------------
__global__ __launch_bounds__(S) void softmax_kernel() {
    int row = blockIdx.x;
    int s = row % S;
    int tid = threadIdx.x;
    __shared__ float red[10];

    float x;
    if (tid <= s) {
        x = 0.f;
        #pragma unroll
        for (int sp = 0; sp < SK; sp++)
            x += g_attp[(size_t)sp * (B * S * S) + (size_t)row * S + tid];
    } else {
        x = -1e30f;
    }
    float m = x;
    #pragma unroll
    for (int o = 16; o; o >>= 1) m = fmaxf(m, __shfl_xor_sync(0xffffffffu, m, o));
    if ((tid & 31) == 0) red[tid >> 5] = m;
    __syncthreads();
    float mall = red[0];
    #pragma unroll
    for (int i = 1; i < 10; i++) mall = fmaxf(mall, red[i]);

    float e = (tid <= s) ? expf(x - mall) : 0.f;
    float ssum = e;
    #pragma unroll
    for (int o = 16; o; o >>= 1) ssum += __shfl_xor_sync(0xffffffffu, ssum, o);
    __syncthreads();
    if ((tid & 31) == 0) red[tid >> 5] = ssum;
    __syncthreads();
    float tot = 0.f;
    #pragma unroll
    for (int i = 0; i < 10; i++) tot += red[i];

    g_attb[(size_t)row * S + tid] = __float2half(e / tot);
}

// ---------------------------------------------------------------------------
// K4: out = att @ V + residual via mma.sync f16.  Tile M=64(s) x N=128(d),
// K = t-blocks of 64 (causal: stile+1 blocks).  2-stage, 48KB smem -> 4 CTAs/SM.
// Epilogue stages acc through smem for fully-coalesced v-read/out-write.
// grid (160, 5, B), 256 threads.
// ---------------------------------------------------------------------------
#define OU_A0 0
#define OU_A1 8192
#define OU_B0 16384
#define OU_B1 32768
#define OU_SMEM 49152
#define STG_STRIDE 132   // fp32 staging row stride (spreads banks: 132*4 mod 128 != 0)

__global__ __launch_bounds__(256) void out_mma(const float* __restrict__ v,
                                               float* __restrict__ out) {
    extern __shared__ char sm[];
    uint32_t sb = smem_u32(sm);
    int ckp = blockIdx.x, stile = blockIdx.y, b = blockIdx.z;
    int s0 = stile * 64, n0 = ckp * 128;
    int tid = threadIdx.x, l = tid & 31, wid = tid >> 5;
    int wm = wid >> 2, wn = wid & 3;    // warp grid 2 (M: 32 rows) x 4 (N: 32 cols)
    int nblocks = stile + 1;

    const __half* pb = g_attb + (size_t)b * S * S;
    const __half* vb = g_vb + (size_t)b * S * D_TOT;

    float acc[2][4][4];
    #pragma unroll
    for (int f = 0; f < 2; f++)
        #pragma unroll
        for (int nf = 0; nf < 4; nf++)
            #pragma unroll
            for (int e = 0; e < 4; e++) acc[f][nf][e] = 0.f;

    const uint32_t AOF[2] = {OU_A0, OU_A1}, BOF[2] = {OU_B0, OU_B1};

    // fill block 0: A = att tile 64x64 (128B rows), B = V tile 64x128 (256B rows)
    {
        #pragma unroll
        for (int j = 0; j < 2; j++) {
            int idx = tid + 256 * j, r = idx >> 3, g = idx & 7;
            cpa16(sb + OU_A0 + r * 128 + ((g ^ (r & 7)) << 4), pb + (size_t)(s0 + r) * S + g * 8);
        }
        #pragma unroll
        for (int j = 0; j < 4; j++) {
            int idx = tid + 256 * j, r = idx >> 4, g = idx & 15;
            cpa16(sb + OU_B0 + r * 256 + ((g ^ (r & 7)) << 4), vb + (size_t)r * D_TOT + n0 + g * 8);
        }
        CP_COMMIT();
    }

    for (int tt = 0; tt < nblocks; tt++) {
        int buf = tt & 1;
        if (tt + 1 < nblocks) {
            int t1 = (tt + 1) * 64;
            uint32_t a_of = AOF[buf ^ 1], b_of = BOF[buf ^ 1];
            #pragma unroll
            for (int j = 0; j < 2; j++) {
                int idx = tid + 256 * j, r = idx >> 3, g = idx & 7;
                cpa16(sb + a_of + r * 128 + ((g ^ (r & 7)) << 4), pb + (size_t)(s0 + r) * S + t1 + g * 8);
            }
            #pragma unroll
            for (int j = 0; j < 4; j++) {
                int idx = tid + 256 * j, r = idx >> 4, g = idx & 15;
                cpa16(sb + b_of + r * 256 + ((g ^ (r & 7)) << 4), vb + (size_t)(t1 + r) * D_TOT + n0 + g * 8);
            }
            CP_COMMIT();
            CP_WAIT1();
        } else {
            CP_WAIT0();
        }
        __syncthreads();
        uint32_t Ab = sb + AOF[buf], Bb = sb + BOF[buf];
        #pragma unroll
        for (int kk = 0; kk < 4; kk++) {
            uint32_t af[2][4], bfr[2][4];
            #pragma unroll
            for (int f = 0; f < 2; f++) {
                int rowA = wm * 32 + f * 16 + (l & 15);
                int g = 2 * kk + (l >> 4);
                ldm4(af[f], Ab + rowA * 128 + ((g ^ (l & 7)) << 4));
            }
            #pragma unroll
            for (int h = 0; h < 2; h++) {
                int rowB = kk * 16 + (l & 15);
                int g = wn * 4 + h * 2 + (l >> 4);
                ldm4t(bfr[h], Bb + rowB * 256 + ((g ^ (rowB & 7)) << 4));
            }
            #pragma unroll
            for (int f = 0; f < 2; f++)
                #pragma unroll
                for (int nf = 0; nf < 4; nf++)
                    mma_f16(acc[f][nf], af[f], &bfr[nf >> 1][(nf & 1) * 2]);
        }
        __syncthreads();
    }

    // ---- epilogue: stage acc -> smem, then coalesced residual+store ----
    float* stage = (float*)sm;   // 64 x STG_STRIDE fp32 = 33792 B (smem free now)
    #pragma unroll
    for (int f = 0; f < 2; f++) {
        #pragma unroll
        for (int half = 0; half < 2; half++) {
            int r = wm * 32 + f * 16 + (l >> 2) + half * 8;   // 0..63
            #pragma unroll
            for (int nf = 0; nf < 4; nf++) {
                int col = wn * 32 + nf * 8 + (l & 3) * 2;
                stage[r * STG_STRIDE + col]     = acc[f][nf][half * 2 + 0];
                stage[r * STG_STRIDE + col + 1] = acc[f][nf][half * 2 + 1];
            }
        }
    }
    __syncthreads();
    // block-wide coalesced copy: 64 rows x 128 floats = 2048 float4
    #pragma unroll
    for (int j = 0; j < 8; j++) {
        int idx = tid + 256 * j;
        int r = idx >> 5, pos = idx & 31;      // pos: float4 index within row
        int d = pos * 4;                        // 0..124
        int ck = ckp * 2 + (d >> 6), w = d & 63;
        size_t g = elem_base(b, s0 + r, ck) + w;
        float4 a = *(const float4*)&stage[r * STG_STRIDE + d];
        float4 vv = *(const float4*)(v + g);
        float4 o;
        o.x = a.x + vv.x;
        o.y = a.y + vv.y;
        o.z = a.z + vv.z;
        o.w = a.w + vv.w;
        *(float4*)(out + g) = o;
    }
}

// ---------------------------------------------------------------------------
extern "C" void kernel_launch(void* const* d_in, const int* in_sizes, int n_in,
                              void* d_out, int out_size) {
    const float* q = (const float*)d_in[0];
    const float* k = (const float*)d_in[1];
    const float* v = (const float*)d_in[2];
    float* out = (float*)d_out;

    static bool attr_done = false;
    if (!attr_done) {
        cudaFuncSetAttribute(scores_mma, cudaFuncAttributeMaxDynamicSharedMemorySize, SC_SMEM);
        cudaFuncSetAttribute(out_mma, cudaFuncAttributeMaxDynamicSharedMemorySize, OU_SMEM);
        attr_done = true;
    }

    convnorm_kernel<<<dim3(B * S, 3), 256>>>(q, k, v);
    scores_mma<<<dim3(9, SK, B), 256, SC_SMEM>>>();
    softmax_kernel<<<B * S, S>>>();
    out_mma<<<dim3(160, 5, B), 256, OU_SMEM>>>(v, out);
}

// round 16
// speedup vs baseline: 1.5199x; 1.0013x over previous
#include <cuda_runtime.h>
#include <cuda_fp16.h>
#include <math.h>
#include <cstdint>

// Problem constants
#define B 4
#define C 64
#define NA 25
#define H 64
#define W 64
#define S 320        // H*U
#define NCHUNK 320   // chunks of 64 floats along w
#define D_TOT 20480  // feature dim
#define BSTRIDE 6553600
#define CSTRIDE 102400
#define NSTRIDE 4096
#define SK 16                       // split-K for scores
#define KSTEPS (D_TOT / SK / 64)    // 20 K-blocks of 64 per split

typedef unsigned long long u64;

// ---- scratch (device globals; no allocations allowed) ----
__device__ float g_rq[B * S];
__device__ float g_rk[B * S];
__device__ __half g_attp[(size_t)SK * B * S * S];  // split-K partial scores (f16)
__device__ __half g_attb[(size_t)B * S * S];       // softmax probs (f16)
__device__ __half g_qb[(size_t)B * S * D_TOT];
__device__ __half g_kb[(size_t)B * S * D_TOT];
__device__ __half g_vb[(size_t)B * S * D_TOT];

// original-layout address of (b, s, chunk ck, w=0)
__device__ __forceinline__ size_t elem_base(int b, int s, int ck) {
    int h = s / 5, uu = s - h * 5;
    int c = ck / 5, vv = ck - c * 5;
    return (size_t)b * BSTRIDE + (size_t)c * CSTRIDE + (size_t)(uu * 5 + vv) * NSTRIDE + (size_t)h * W;
}

// ---- PTX helpers (sm_80-level: valid at virtual target sm_103) ----
__device__ __forceinline__ uint32_t smem_u32(const void* p) {
    uint32_t a;
    asm("{ .reg .u64 t; cvta.to.shared.u64 t, %1; cvt.u32.u64 %0, t; }" : "=r"(a) : "l"(p));
    return a;
}
__device__ __forceinline__ void cpa16(uint32_t dst, const void* src) {
    asm volatile("{ .reg .u64 g; cvta.to.global.u64 g, %1; cp.async.cg.shared.global [%0], [g], 16; }"
                 :: "r"(dst), "l"(src) : "memory");
}
#define CP_COMMIT() asm volatile("cp.async.commit_group;" ::: "memory")
#define CP_WAIT0()  asm volatile("cp.async.wait_group 0;" ::: "memory")
#define CP_WAIT1()  asm volatile("cp.async.wait_group 1;" ::: "memory")

__device__ __forceinline__ void ldm4(uint32_t* r, uint32_t addr) {
    asm volatile("ldmatrix.sync.aligned.m8n8.x4.shared.b16 {%0,%1,%2,%3}, [%4];"
                 : "=r"(r[0]), "=r"(r[1]), "=r"(r[2]), "=r"(r[3]) : "r"(addr));
}
__device__ __forceinline__ void ldm4t(uint32_t* r, uint32_t addr) {
    asm volatile("ldmatrix.sync.aligned.m8n8.x4.trans.shared.b16 {%0,%1,%2,%3}, [%4];"
                 : "=r"(r[0]), "=r"(r[1]), "=r"(r[2]), "=r"(r[3]) : "r"(addr));
}
__device__ __forceinline__ void mma_f16(float* d, const uint32_t* a, const uint32_t* b) {
    asm volatile("mma.sync.aligned.m16n8k16.row.col.f32.f16.f16.f32 "
                 "{%0,%1,%2,%3}, {%4,%5,%6,%7}, {%8,%9}, {%0,%1,%2,%3};"
                 : "+f"(d[0]), "+f"(d[1]), "+f"(d[2]), "+f"(d[3])
                 : "r"(a[0]), "r"(a[1]), "r"(a[2]), "r"(a[3]), "r"(b[0]), "r"(b[1]));
}

// pack 8 f32 -> 8 f16 in a uint4
__device__ __forceinline__ uint4 pack8(float4 x0, float4 x1) {
    uint4 wv;
    __half2 p0 = __floats2half2_rn(x0.x, x0.y);
    __half2 p1 = __floats2half2_rn(x0.z, x0.w);
    __half2 p2 = __floats2half2_rn(x1.x, x1.y);
    __half2 p3 = __floats2half2_rn(x1.z, x1.w);
    *reinterpret_cast<__half2*>(&wv.x) = p0;
    *reinterpret_cast<__half2*>(&wv.y) = p1;
    *reinterpret_cast<__half2*>(&wv.z) = p2;
    *reinterpret_cast<__half2*>(&wv.w) = p3;
    return wv;
}

// ---------------------------------------------------------------------------
// K1: fused gather + f16 convert (Q, K, V) + row inverse-norms (Q, K).
// grid (B*S, 3), 256 threads.  16 floats/thread/iter (4 independent LDG.128).
// ---------------------------------------------------------------------------
__global__ __launch_bounds__(256) void convnorm_kernel(const float* __restrict__ q,
                                                       const float* __restrict__ k,
                                                       const float* __restrict__ v) {
    int row = blockIdx.x;
    int which = blockIdx.y;
    const float* src = (which == 0) ? q : (which == 1) ? k : v;
    __half* dstb = (which == 0) ? g_qb : (which == 1) ? g_kb : g_vb;
    int b = row / S, s = row - b * S;

    uint4* drow = (uint4*)(dstb + (size_t)row * D_TOT);
    float acc = 0.f;
    for (int i = threadIdx.x; i < NCHUNK * 4; i += 256) {
        int ck = i >> 2, q16 = i & 3;
        const float* base = src + elem_base(b, s, ck) + q16 * 16;
        float4 x0 = *(const float4*)base;
        float4 x1 = *(const float4*)(base + 4);
        float4 x2 = *(const float4*)(base + 8);
        float4 x3 = *(const float4*)(base + 12);
        acc += x0.x * x0.x + x0.y * x0.y + x0.z * x0.z + x0.w * x0.w
             + x1.x * x1.x + x1.y * x1.y + x1.z * x1.z + x1.w * x1.w
             + x2.x * x2.x + x2.y * x2.y + x2.z * x2.z + x2.w * x2.w
             + x3.x * x3.x + x3.y * x3.y + x3.z * x3.z + x3.w * x3.w;
        drow[2 * i]     = pack8(x0, x1);
        drow[2 * i + 1] = pack8(x2, x3);
    }
    if (which < 2) {
        __shared__ float red[256];
        red[threadIdx.x] = acc;
        __syncthreads();
        for (int off = 128; off; off >>= 1) {
            if (threadIdx.x < off) red[threadIdx.x] += red[threadIdx.x + off];
            __syncthreads();
        }
        if (threadIdx.x == 0)
            (which ? g_rk : g_rq)[row] = 1.f / fmaxf(sqrtf(red[0]), 1e-12f);
    }
}

// ---------------------------------------------------------------------------
// K2: scores = Q K^T via mma.sync f16.  Tile M=64 x N=128 (causal 9-tile list).
// K-blocks of 64, split-K=16.  f16 split partials.  48KB smem, 4 CTAs/SM.
// grid (9 tiles, 16 splits, B), 256 threads.
// ---------------------------------------------------------------------------
#define SC_A0 0
#define SC_A1 8192
#define SC_B0 16384
#define SC_B1 32768
#define SC_SMEM 49152

__global__ __launch_bounds__(256, 4) void scores_mma() {
    extern __shared__ char sm[];
    uint32_t sb = smem_u32(sm);
    const int MI[9] = {0, 1, 2, 2, 3, 3, 4, 4, 4};
    const int NJ[9] = {0, 0, 0, 1, 0, 1, 0, 1, 2};
    int tile = blockIdx.x, split = blockIdx.y, b = blockIdx.z;
    int s0 = MI[tile] * 64, t0 = NJ[tile] * 128;
    int tid = threadIdx.x, l = tid & 31, wid = tid >> 5;
    int wm = wid >> 2, wn = wid & 3;    // warp grid 2 (M: 32 rows) x 4 (N: 32 cols)
    int d_base = split * (D_TOT / SK);

    const __half* qrow = g_qb + (size_t)b * S * D_TOT;
    const __half* krow = g_kb + (size_t)b * S * D_TOT;

    float acc[2][4][4];
    #pragma unroll
    for (int f = 0; f < 2; f++)
        #pragma unroll
        for (int nf = 0; nf < 4; nf++)
            #pragma unroll
            for (int e = 0; e < 4; e++) acc[f][nf][e] = 0.f;

    const uint32_t AOF[2] = {SC_A0, SC_A1}, BOF[2] = {SC_B0, SC_B1};

    // fill step 0: A = 64x64 f16 (128B rows), B = 128x64 f16 (128B rows)
    {
        int d0 = d_base;
        #pragma unroll
        for (int j = 0; j < 2; j++) {
            int idx = tid + 256 * j, r = idx >> 3, g = idx & 7;
            cpa16(sb + SC_A0 + r * 128 + ((g ^ (r & 7)) << 4), qrow + (size_t)(s0 + r) * D_TOT + d0 + g * 8);
        }
        #pragma unroll
        for (int j = 0; j < 4; j++) {
            int idx = tid + 256 * j, r = idx >> 3, g = idx & 7;
            int t = t0 + r; if (t >= S) t = S - 1;
            cpa16(sb + SC_B0 + r * 128 + ((g ^ (r & 7)) << 4), krow + (size_t)t * D_TOT + d0 + g * 8);
        }
        CP_COMMIT();
    }

    for (int step = 0; step < KSTEPS; step++) {
        int buf = step & 1;
        if (step + 1 < KSTEPS) {
            int d0 = d_base + (step + 1) * 64;
            uint32_t a_of = AOF[buf ^ 1], b_of = BOF[buf ^ 1];
            #pragma unroll
            for (int j = 0; j < 2; j++) {
                int idx = tid + 256 * j, r = idx >> 3, g = idx & 7;
                cpa16(sb + a_of + r * 128 + ((g ^ (r & 7)) << 4), qrow + (size_t)(s0 + r) * D_TOT + d0 + g * 8);
            }
            #pragma unroll
            for (int j = 0; j < 4; j++) {
                int idx = tid + 256 * j, r = idx >> 3, g = idx & 7;
                int t = t0 + r; if (t >= S) t = S - 1;
                cpa16(sb + b_of + r * 128 + ((g ^ (r & 7)) << 4), krow + (size_t)t * D_TOT + d0 + g * 8);
            }
            CP_COMMIT();
            CP_WAIT1();
        } else {
            CP_WAIT0();
        }
        __syncthreads();
        uint32_t Ab = sb + AOF[buf], Bb = sb + BOF[buf];
        #pragma unroll
        for (int kk = 0; kk < 4; kk++) {
            uint32_t af[2][4], bfr[2][4];
            #pragma unroll
            for (int f = 0; f < 2; f++) {
                int rowA = wm * 32 + f * 16 + (l & 15);
                int g = 2 * kk + (l >> 4);
                ldm4(af[f], Ab + rowA * 128 + ((g ^ (l & 7)) << 4));
            }
            #pragma unroll
            for (int h = 0; h < 2; h++) {
                int rowB = wn * 32 + h * 16 + (l & 7) + ((l >> 4) << 3);
                int g = 2 * kk + ((l >> 3) & 1);
                ldm4(bfr[h], Bb + rowB * 128 + ((g ^ (rowB & 7)) << 4));
            }
            #pragma unroll
            for (int f = 0; f < 2; f++)
                #pragma unroll
                for (int nf = 0; nf < 4; nf++)
                    mma_f16(acc[f][nf], af[f], &bfr[nf >> 1][(nf & 1) * 2]);
        }
        __syncthreads();
    }

    // epilogue: apply rq*rk, store f16 split partials
    __half* outp = g_attp + (size_t)split * (B * S * S) + (size_t)b * S * S;
    #pragma unroll
    for (int f = 0; f < 2; f++) {
        int r0 = s0 + wm * 32 + f * 16 + (l >> 2);
        #pragma unroll
        for (int half = 0; half < 2; half++) {
            int s = r0 + half * 8;
            float rq = __ldg(&g_rq[b * S + s]);
            #pragma unroll
            for (int nf = 0; nf < 4; nf++) {
                int t = t0 + wn * 32 + nf * 8 + (l & 3) * 2;
                if (t < S) {
                    float ox = acc[f][nf][half * 2 + 0] * rq * __ldg(&g_rk[b * S + t]);
                    float oy = acc[f][nf][half * 2 + 1] * rq * __ldg(&g_rk[b * S + t + 1]);
                    *(__half2*)(outp + (size_t)s * S + t) = __floats2half2_rn(ox, oy);
                }
            }
        }
    }
}

// ---------------------------------------------------------------------------
// K3: split-K reduce (f16 partials) + causal softmax -> f16 probabilities.
// grid B*S, 320 threads.
// ---------------------------------------------------------------------------
__global__ __launch_bounds__(S) void softmax_kernel() {
    int row = blockIdx.x;
    int s = row % S;
    int tid = threadIdx.x;
    __shared__ float red[10];

    float x;
    if (tid <= s) {
        x = 0.f;
        #pragma unroll
        for (int sp = 0; sp < SK; sp++)
            x += __half2float(g_attp[(size_t)sp * (B * S * S) + (size_t)row * S + tid]);
    } else {
        x = -1e30f;
    }
    float m = x;
    #pragma unroll
    for (int o = 16; o; o >>= 1) m = fmaxf(m, __shfl_xor_sync(0xffffffffu, m, o));
    if ((tid & 31) == 0) red[tid >> 5] = m;
    __syncthreads();
    float mall = red[0];
    #pragma unroll
    for (int i = 1; i < 10; i++) mall = fmaxf(mall, red[i]);

    float e = (tid <= s) ? expf(x - mall) : 0.f;
    float ssum = e;
    #pragma unroll
    for (int o = 16; o; o >>= 1) ssum += __shfl_xor_sync(0xffffffffu, ssum, o);
    __syncthreads();
    if ((tid & 31) == 0) red[tid >> 5] = ssum;
    __syncthreads();
    float tot = 0.f;
    #pragma unroll
    for (int i = 0; i < 10; i++) tot += red[i];

    g_attb[(size_t)row * S + tid] = __float2half(e / tot);
}

// ---------------------------------------------------------------------------
// K4: out = att @ V + residual via mma.sync f16.  Tile M=64(s) x N=128(d),
// K = t-blocks of 64 (causal: stile+1 blocks).  2-stage, 48KB smem, 4 CTAs/SM.
// Epilogue stages acc through smem for fully-coalesced v-read/out-write.
// grid (160, 5, B), 256 threads.
// ---------------------------------------------------------------------------
#define OU_A0 0
#define OU_A1 8192
#define OU_B0 16384
#define OU_B1 32768
#define OU_SMEM 49152
#define STG_STRIDE 132   // fp32 staging row stride (spreads banks)

__global__ __launch_bounds__(256, 4) void out_mma(const float* __restrict__ v,
                                                  float* __restrict__ out) {
    extern __shared__ char sm[];
    uint32_t sb = smem_u32(sm);
    int ckp = blockIdx.x, stile = blockIdx.y, b = blockIdx.z;
    int s0 = stile * 64, n0 = ckp * 128;
    int tid = threadIdx.x, l = tid & 31, wid = tid >> 5;
    int wm = wid >> 2, wn = wid & 3;    // warp grid 2 (M: 32 rows) x 4 (N: 32 cols)
    int nblocks = stile + 1;

    const __half* pb = g_attb + (size_t)b * S * S;
    const __half* vb = g_vb + (size_t)b * S * D_TOT;

    float acc[2][4][4];
    #pragma unroll
    for (int f = 0; f < 2; f++)
        #pragma unroll
        for (int nf = 0; nf < 4; nf++)
            #pragma unroll
            for (int e = 0; e < 4; e++) acc[f][nf][e] = 0.f;

    const uint32_t AOF[2] = {OU_A0, OU_A1}, BOF[2] = {OU_B0, OU_B1};

    // fill block 0: A = att tile 64x64 (128B rows), B = V tile 64x128 (256B rows)
    {
        #pragma unroll
        for (int j = 0; j < 2; j++) {
            int idx = tid + 256 * j, r = idx >> 3, g = idx & 7;
            cpa16(sb + OU_A0 + r * 128 + ((g ^ (r & 7)) << 4), pb + (size_t)(s0 + r) * S + g * 8);
        }
        #pragma unroll
        for (int j = 0; j < 4; j++) {
            int idx = tid + 256 * j, r = idx >> 4, g = idx & 15;
            cpa16(sb + OU_B0 + r * 256 + ((g ^ (r & 7)) << 4), vb + (size_t)r * D_TOT + n0 + g * 8);
        }
        CP_COMMIT();
    }

    for (int tt = 0; tt < nblocks; tt++) {
        int buf = tt & 1;
        if (tt + 1 < nblocks) {
            int t1 = (tt + 1) * 64;
            uint32_t a_of = AOF[buf ^ 1], b_of = BOF[buf ^ 1];
            #pragma unroll
            for (int j = 0; j < 2; j++) {
                int idx = tid + 256 * j, r = idx >> 3, g = idx & 7;
                cpa16(sb + a_of + r * 128 + ((g ^ (r & 7)) << 4), pb + (size_t)(s0 + r) * S + t1 + g * 8);
            }
            #pragma unroll
            for (int j = 0; j < 4; j++) {
                int idx = tid + 256 * j, r = idx >> 4, g = idx & 15;
                cpa16(sb + b_of + r * 256 + ((g ^ (r & 7)) << 4), vb + (size_t)(t1 + r) * D_TOT + n0 + g * 8);
            }
            CP_COMMIT();
            CP_WAIT1();
        } else {
            CP_WAIT0();
        }
        __syncthreads();
        uint32_t Ab = sb + AOF[buf], Bb = sb + BOF[buf];
        #pragma unroll
        for (int kk = 0; kk < 4; kk++) {
            uint32_t af[2][4], bfr[2][4];
            #pragma unroll
            for (int f = 0; f < 2; f++) {
                int rowA = wm * 32 + f * 16 + (l & 15);
                int g = 2 * kk + (l >> 4);
                ldm4(af[f], Ab + rowA * 128 + ((g ^ (l & 7)) << 4));
            }
            #pragma unroll
            for (int h = 0; h < 2; h++) {
                int rowB = kk * 16 + (l & 15);
                int g = wn * 4 + h * 2 + (l >> 4);
                ldm4t(bfr[h], Bb + rowB * 256 + ((g ^ (rowB & 7)) << 4));
            }
            #pragma unroll
            for (int f = 0; f < 2; f++)
                #pragma unroll
                for (int nf = 0; nf < 4; nf++)
                    mma_f16(acc[f][nf], af[f], &bfr[nf >> 1][(nf & 1) * 2]);
        }
        __syncthreads();
    }

    // ---- epilogue: stage acc -> smem, then coalesced residual+store ----
    float* stage = (float*)sm;   // 64 x STG_STRIDE fp32 = 33792 B (smem free now)
    #pragma unroll
    for (int f = 0; f < 2; f++) {
        #pragma unroll
        for (int half = 0; half < 2; half++) {
            int r = wm * 32 + f * 16 + (l >> 2) + half * 8;   // 0..63
            #pragma unroll
            for (int nf = 0; nf < 4; nf++) {
                int col = wn * 32 + nf * 8 + (l & 3) * 2;
                stage[r * STG_STRIDE + col]     = acc[f][nf][half * 2 + 0];
                stage[r * STG_STRIDE + col + 1] = acc[f][nf][half * 2 + 1];
            }
        }
    }
    __syncthreads();
    // block-wide coalesced copy: 64 rows x 128 floats = 2048 float4
    #pragma unroll
    for (int j = 0; j < 8; j++) {
        int idx = tid + 256 * j;
        int r = idx >> 5, pos = idx & 31;      // pos: float4 index within row
        int d = pos * 4;                        // 0..124
        int ck = ckp * 2 + (d >> 6), w = d & 63;
        size_t g = elem_base(b, s0 + r, ck) + w;
        float4 a = *(const float4*)&stage[r * STG_STRIDE + d];
        float4 vv = *(const float4*)(v + g);
        float4 o;
        o.x = a.x + vv.x;
        o.y = a.y + vv.y;
        o.z = a.z + vv.z;
        o.w = a.w + vv.w;
        *(float4*)(out + g) = o;
    }
}

// ---------------------------------------------------------------------------
extern "C" void kernel_launch(void* const* d_in, const int* in_sizes, int n_in,
                              void* d_out, int out_size) {
    const float* q = (const float*)d_in[0];
    const float* k = (const float*)d_in[1];
    const float* v = (const float*)d_in[2];
    float* out = (float*)d_out;

    static bool attr_done = false;
    if (!attr_done) {
        cudaFuncSetAttribute(scores_mma, cudaFuncAttributeMaxDynamicSharedMemorySize, SC_SMEM);
        cudaFuncSetAttribute(out_mma, cudaFuncAttributeMaxDynamicSharedMemorySize, OU_SMEM);
        attr_done = true;
    }

    convnorm_kernel<<<dim3(B * S, 3), 256>>>(q, k, v);
    scores_mma<<<dim3(9, SK, B), 256, SC_SMEM>>>();
    softmax_kernel<<<B * S, S>>>();
    out_mma<<<dim3(160, 5, B), 256, OU_SMEM>>>(v, out);
}